// round 2
// baseline (speedup 1.0000x reference)
#include <cuda_runtime.h>
#include <cuda_bf16.h>

// ---------------------------------------------------------------------------
// Problem constants
// ---------------------------------------------------------------------------
#define NN    8192          // B*S nodes
#define DD    768           // hidden dim
#define HH    12            // heads
#define HDIM  64            // head dim
#define EE    131072        // edges
#define NSTEP 5

// ---------------------------------------------------------------------------
// Scratch (static device globals — no allocation allowed)
// ---------------------------------------------------------------------------
__device__ float g_q[NN * DD];
__device__ float g_k[NN * DD];
__device__ float g_v[NN * DD];
__device__ float g_ha[NN * DD];
__device__ float g_hb[NN * DD];
__device__ float g_y[NN * DD];

__device__ float g_score[EE * HH];       // scores, then pexp in place
__device__ float g_smax[NN * HH];
__device__ float g_denom[NN * HH];

__device__ int   g_cnt[NN];
__device__ int   g_rowptr[NN + 1];
__device__ int   g_pos[EE];              // CSR slot of each edge
__device__ int   g_csr_src[EE];          // src node per CSR slot
__device__ float g_csr_attn[EE * HH];    // attn reordered into CSR order

// ---------------------------------------------------------------------------
// Helpers
// ---------------------------------------------------------------------------
__device__ __forceinline__ void atomicMaxFloat(float* addr, float val) {
    if (val >= 0.0f) atomicMax((int*)addr, __float_as_int(val));
    else             atomicMin((unsigned int*)addr, __float_as_uint(val));
}

// ---------------------------------------------------------------------------
// SGEMM (NT): C[i,j] = (sum_k A[i,k]*W[j,k] + bias[j]) * scale + resid[i,j]
// A: [M,K] row-major, W: [Nn,K] row-major. Tiles 128x128x8, 256 thr, 8x8/thr.
// ---------------------------------------------------------------------------
#define BM 128
#define BN 128
#define BK 8
#define TM 8
#define TN 8

__global__ __launch_bounds__(256) void gemm_nt(
    const float* __restrict__ A, const float* __restrict__ W,
    const float* __restrict__ bias, const float* __restrict__ resid,
    float* __restrict__ C, int M, int Nn, int K, float scale)
{
    __shared__ float As[BK][BM];
    __shared__ float Ws[BK][BN];

    const int tid  = threadIdx.x;
    const int bm   = blockIdx.y * BM;
    const int bn   = blockIdx.x * BN;

    const int lrow = tid >> 1;            // 0..127
    const int lcol = (tid & 1) * 4;       // 0 or 4

    const float* Aptr = A + (size_t)(bm + lrow) * K + lcol;
    const float* Wptr = W + (size_t)(bn + lrow) * K + lcol;

    const int tx = tid & 15;              // 0..15 (col group)
    const int ty = tid >> 4;              // 0..15 (row group)

    float acc[TM][TN];
    #pragma unroll
    for (int i = 0; i < TM; i++)
        #pragma unroll
        for (int j = 0; j < TN; j++) acc[i][j] = 0.0f;

    for (int k0 = 0; k0 < K; k0 += BK) {
        float4 av = *(const float4*)(Aptr + k0);
        float4 wv = *(const float4*)(Wptr + k0);
        As[lcol + 0][lrow] = av.x; As[lcol + 1][lrow] = av.y;
        As[lcol + 2][lrow] = av.z; As[lcol + 3][lrow] = av.w;
        Ws[lcol + 0][lrow] = wv.x; Ws[lcol + 1][lrow] = wv.y;
        Ws[lcol + 2][lrow] = wv.z; Ws[lcol + 3][lrow] = wv.w;
        __syncthreads();

        #pragma unroll
        for (int kk = 0; kk < BK; kk++) {
            float a[TM], b[TN];
            #pragma unroll
            for (int i = 0; i < TM; i++) a[i] = As[kk][ty * TM + i];
            #pragma unroll
            for (int j = 0; j < TN; j++) b[j] = Ws[kk][tx * TN + j];
            #pragma unroll
            for (int i = 0; i < TM; i++)
                #pragma unroll
                for (int j = 0; j < TN; j++) acc[i][j] += a[i] * b[j];
        }
        __syncthreads();
    }

    #pragma unroll
    for (int i = 0; i < TM; i++) {
        const int r = bm + ty * TM + i;
        #pragma unroll
        for (int j = 0; j < TN; j++) {
            const int c = bn + tx * TN + j;
            float v = (acc[i][j] + bias[c]) * scale;
            if (resid) v += resid[(size_t)r * Nn + c];
            C[(size_t)r * Nn + c] = v;
        }
    }
}

// ---------------------------------------------------------------------------
// init: smax = -inf-ish, denom = 0, counts = 0
// ---------------------------------------------------------------------------
__global__ void init_kernel() {
    int i = blockIdx.x * blockDim.x + threadIdx.x;
    if (i < NN * HH) { g_smax[i] = -3.0e38f; g_denom[i] = 0.0f; }
    if (i < NN) g_cnt[i] = 0;
}

__global__ void count_kernel(const int* __restrict__ dst) {
    int e = blockIdx.x * blockDim.x + threadIdx.x;
    if (e < EE) atomicAdd(&g_cnt[dst[e]], 1);
}

// single-block exclusive scan over 8192 counts (1024 thr x 8 each)
__global__ __launch_bounds__(1024) void scan_kernel() {
    __shared__ int ssum[1024];
    const int t = threadIdx.x;
    const int base = t * 8;
    int local[8];
    int s = 0;
    #pragma unroll
    for (int i = 0; i < 8; i++) { local[i] = g_cnt[base + i]; s += local[i]; }
    ssum[t] = s;
    __syncthreads();
    for (int off = 1; off < 1024; off <<= 1) {
        int v = (t >= off) ? ssum[t - off] : 0;
        __syncthreads();
        ssum[t] += v;
        __syncthreads();
    }
    int pre = (t == 0) ? 0 : ssum[t - 1];
    #pragma unroll
    for (int i = 0; i < 8; i++) {
        g_rowptr[base + i] = pre;
        pre += local[i];
        g_cnt[base + i] = 0;               // reset for scatter pass
    }
    if (t == 1023) g_rowptr[NN] = pre;
}

__global__ void scatter_kernel(const int* __restrict__ src,
                               const int* __restrict__ dst) {
    int e = blockIdx.x * blockDim.x + threadIdx.x;
    if (e < EE) {
        int d = dst[e];
        int pos = g_rowptr[d] + atomicAdd(&g_cnt[d], 1);
        g_pos[e] = pos;
        g_csr_src[pos] = src[e];
    }
}

// ---------------------------------------------------------------------------
// scores: one warp per edge; 12 head-dots of 64; atomicMax into smax
// ---------------------------------------------------------------------------
__global__ __launch_bounds__(256) void score_kernel(
    const int* __restrict__ src, const int* __restrict__ dst,
    const float* __restrict__ am)
{
    const int gw   = (blockIdx.x * blockDim.x + threadIdx.x) >> 5;
    const int lane = threadIdx.x & 31;
    if (gw >= EE) return;
    const int s = src[gw];
    const int d = dst[gw];
    const float* kr = g_k + (size_t)s * DD;
    const float* qr = g_q + (size_t)d * DD;
    const bool m = (am[d] >= 0.0f);

    #pragma unroll
    for (int h = 0; h < HH; h++) {
        const int i0 = h * HDIM + lane;
        float p = kr[i0] * qr[i0] + kr[i0 + 32] * qr[i0 + 32];
        #pragma unroll
        for (int off = 16; off; off >>= 1)
            p += __shfl_xor_sync(0xFFFFFFFFu, p, off);
        if (lane == 0) {
            float sc = m ? p : -1.0e4f;
            g_score[gw * HH + h] = sc;
            atomicMaxFloat(&g_smax[d * HH + h], sc);
        }
    }
}

__global__ void exp_kernel(const int* __restrict__ dst) {
    int i = blockIdx.x * blockDim.x + threadIdx.x;
    if (i < EE * HH) {
        int e = i / HH;
        int h = i - e * HH;
        int d = dst[e];
        float p = __expf(g_score[i] - g_smax[d * HH + h]);
        g_score[i] = p;
        atomicAdd(&g_denom[d * HH + h], p);
    }
}

__global__ void attn_kernel(const int* __restrict__ dst) {
    int i = blockIdx.x * blockDim.x + threadIdx.x;
    if (i < EE * HH) {
        int e = i / HH;
        int h = i - e * HH;
        int d = dst[e];
        g_csr_attn[(size_t)g_pos[e] * HH + h] = g_score[i] / g_denom[d * HH + h];
    }
}

// ---------------------------------------------------------------------------
// one MP step: hout[n] = 0.9 * sum_{e:dst=n} attn[e]*hin[src_e] + 0.1 * v[n]
// block = dst node (256 thr, 3 dims each), CSR gather, no atomics.
// FIXED: s_attn staging now covers all c*HH (up to 384) entries via strided loop.
// ---------------------------------------------------------------------------
#define CHUNK 32
__global__ __launch_bounds__(256) void agg_kernel(
    const float* __restrict__ hin, float* __restrict__ hout)
{
    const int node = blockIdx.x;
    const int t    = threadIdx.x;
    const int beg  = g_rowptr[node];
    const int end  = g_rowptr[node + 1];

    const int h0 = t >> 6;
    const int h1 = (t + 256) >> 6;
    const int h2 = (t + 512) >> 6;

    float a0 = 0.0f, a1 = 0.0f, a2 = 0.0f;

    __shared__ int   s_src[CHUNK];
    __shared__ float s_attn[CHUNK * HH];

    for (int cs = beg; cs < end; cs += CHUNK) {
        const int c = min(CHUNK, end - cs);
        __syncthreads();
        if (t < c) s_src[t] = g_csr_src[cs + t];
        for (int i = t; i < c * HH; i += 256)
            s_attn[i] = g_csr_attn[(size_t)cs * HH + i];
        __syncthreads();
        #pragma unroll 4
        for (int j = 0; j < c; j++) {
            const float* hr = hin + (size_t)s_src[j] * DD;
            a0 += s_attn[j * HH + h0] * hr[t];
            a1 += s_attn[j * HH + h1] * hr[t + 256];
            a2 += s_attn[j * HH + h2] * hr[t + 512];
        }
    }

    const size_t base = (size_t)node * DD;
    hout[base + t]       = 0.9f * a0 + 0.1f * g_v[base + t];
    hout[base + t + 256] = 0.9f * a1 + 0.1f * g_v[base + t + 256];
    hout[base + t + 512] = 0.9f * a2 + 0.1f * g_v[base + t + 512];
}

// ---------------------------------------------------------------------------
// LayerNorm: block per row, 256 thr x 3 dims
// ---------------------------------------------------------------------------
__global__ __launch_bounds__(256) void ln_kernel(
    const float* __restrict__ y, const float* __restrict__ gamma,
    const float* __restrict__ beta, float* __restrict__ out)
{
    const int row = blockIdx.x;
    const int t   = threadIdx.x;
    const size_t base = (size_t)row * DD;

    const float x0 = y[base + t];
    const float x1 = y[base + t + 256];
    const float x2 = y[base + t + 512];

    __shared__ float sdata[256];
    sdata[t] = x0 + x1 + x2;
    __syncthreads();
    for (int off = 128; off > 0; off >>= 1) {
        if (t < off) sdata[t] += sdata[t + off];
        __syncthreads();
    }
    const float mu = sdata[0] * (1.0f / DD);
    __syncthreads();

    const float d0 = x0 - mu, d1 = x1 - mu, d2 = x2 - mu;
    sdata[t] = d0 * d0 + d1 * d1 + d2 * d2;
    __syncthreads();
    for (int off = 128; off > 0; off >>= 1) {
        if (t < off) sdata[t] += sdata[t + off];
        __syncthreads();
    }
    const float inv = rsqrtf(sdata[0] * (1.0f / DD) + 1e-12f);

    out[base + t]       = d0 * inv * gamma[t]       + beta[t];
    out[base + t + 256] = d1 * inv * gamma[t + 256] + beta[t + 256];
    out[base + t + 512] = d2 * inv * gamma[t + 512] + beta[t + 512];
}

// ---------------------------------------------------------------------------
// launch
// ---------------------------------------------------------------------------
static float* symF(const void* sym) {
    void* p = nullptr;
    cudaGetSymbolAddress(&p, sym);
    return (float*)p;
}

extern "C" void kernel_launch(void* const* d_in, const int* in_sizes, int n_in,
                              void* d_out, int out_size) {
    const float* x    = (const float*)d_in[0];
    const float* am   = (const float*)d_in[1];
    const int*   esrc = (const int*)d_in[2];
    const int*   edst = (const int*)d_in[3];
    const float* Wq   = (const float*)d_in[4];
    const float* bq   = (const float*)d_in[5];
    const float* Wk   = (const float*)d_in[6];
    const float* bk   = (const float*)d_in[7];
    const float* Wv   = (const float*)d_in[8];
    const float* bv   = (const float*)d_in[9];
    const float* Wo   = (const float*)d_in[10];
    const float* bo   = (const float*)d_in[11];
    const float* lng  = (const float*)d_in[12];
    const float* lnb  = (const float*)d_in[13];
    float* out = (float*)d_out;

    float* q  = symF(g_q);
    float* k  = symF(g_k);
    float* v  = symF(g_v);
    float* ha = symF(g_ha);
    float* hb = symF(g_hb);
    float* y  = symF(g_y);

    const dim3 gemm_grid(DD / BN, NN / BM);

    // projections (q scaled by 1/sqrt(64) = 0.125 after bias, as in reference)
    gemm_nt<<<gemm_grid, 256>>>(x, Wq, bq, nullptr, q, NN, DD, DD, 0.125f);
    gemm_nt<<<gemm_grid, 256>>>(x, Wk, bk, nullptr, k, NN, DD, DD, 1.0f);
    gemm_nt<<<gemm_grid, 256>>>(x, Wv, bv, nullptr, v, NN, DD, DD, 1.0f);

    // CSR build + softmax state init
    init_kernel<<<(NN * HH + 255) / 256, 256>>>();
    count_kernel<<<(EE + 255) / 256, 256>>>(edst);
    scan_kernel<<<1, 1024>>>();
    scatter_kernel<<<(EE + 255) / 256, 256>>>(esrc, edst);

    // edge scores + softmax (attn written in CSR order)
    score_kernel<<<(EE * 32) / 256, 256>>>(esrc, edst, am);
    exp_kernel<<<(EE * HH + 255) / 256, 256>>>(edst);
    attn_kernel<<<(EE * HH + 255) / 256, 256>>>(edst);

    // 5 message-passing steps: v -> ha -> hb -> ha -> hb -> ha
    agg_kernel<<<NN, 256>>>(v,  ha);
    agg_kernel<<<NN, 256>>>(ha, hb);
    agg_kernel<<<NN, 256>>>(hb, ha);
    agg_kernel<<<NN, 256>>>(ha, hb);
    agg_kernel<<<NN, 256>>>(hb, ha);

    // output projection + residual, then LayerNorm
    gemm_nt<<<gemm_grid, 256>>>(ha, Wo, bo, x, y, NN, DD, DD, 1.0f);
    ln_kernel<<<NN, 256>>>(y, lng, lnb, out);
}

// round 4
// speedup vs baseline: 2.0023x; 2.0023x over previous
#include <cuda_runtime.h>
#include <cuda_bf16.h>
#include <cstdint>

// ---------------------------------------------------------------------------
// Problem constants
// ---------------------------------------------------------------------------
#define NN    8192          // B*S nodes
#define DD    768           // hidden dim
#define HH    12            // heads
#define HDIM  64            // head dim
#define EE    131072        // edges

// split-bf16 GEMM constants
#define KSPLIT 2304         // 3*DD (hi|hi|lo vs hi|lo|hi)
#define KC     64           // k elements per smem chunk (bf16) = 128B rows
#define NCHUNK 36           // KSPLIT/KC
#define MT     128          // M tile
#define NT     128          // N tile
#define TILE_BYTES 16384    // 128 rows * 128 bytes
#define GROUPS_PER_ROW (KSPLIT/8)   // 288 16B-units per row

// ---------------------------------------------------------------------------
// Scratch (static device globals — no allocation allowed)
// ---------------------------------------------------------------------------
__device__ float g_q[NN * DD];
__device__ float g_k[NN * DD];
__device__ float g_v[NN * DD];
__device__ float g_ha[NN * DD];
__device__ float g_hb[NN * DD];
__device__ float g_y[NN * DD];

__device__ float g_score[EE * HH];
__device__ float g_smax[NN * HH];
__device__ float g_denom[NN * HH];

__device__ int   g_cnt[NN];
__device__ int   g_rowptr[NN + 1];
__device__ int   g_pos[EE];
__device__ int   g_csr_src[EE];
__device__ float g_csr_attn[EE * HH];

// split-bf16 operand storage (pre-swizzled 16KB tile blocks)
__device__ __align__(128) __nv_bfloat16 g_ax[(size_t)NN * KSPLIT];   // x  split
__device__ __align__(128) __nv_bfloat16 g_ah[(size_t)NN * KSPLIT];   // ha split
__device__ __align__(128) __nv_bfloat16 g_wqs[(size_t)DD * KSPLIT];
__device__ __align__(128) __nv_bfloat16 g_wks[(size_t)DD * KSPLIT];
__device__ __align__(128) __nv_bfloat16 g_wvs[(size_t)DD * KSPLIT];
__device__ __align__(128) __nv_bfloat16 g_wos[(size_t)DD * KSPLIT];

// ---------------------------------------------------------------------------
// helpers
// ---------------------------------------------------------------------------
__device__ __forceinline__ uint32_t smem_u32(const void* p) {
    uint32_t a;
    asm("{ .reg .u64 t; cvta.to.shared.u64 t, %1; cvt.u32.u64 %0, t; }"
        : "=r"(a) : "l"(p));
    return a;
}

__device__ __forceinline__ void ldmx4(uint32_t* r, uint32_t addr) {
    asm volatile("ldmatrix.sync.aligned.m8n8.x4.shared.b16 {%0,%1,%2,%3}, [%4];"
        : "=r"(r[0]), "=r"(r[1]), "=r"(r[2]), "=r"(r[3]) : "r"(addr));
}

__device__ __forceinline__ void mma_bf16(float* c, const uint32_t* a,
                                         uint32_t b0, uint32_t b1) {
    asm volatile(
        "mma.sync.aligned.m16n8k16.row.col.f32.bf16.bf16.f32 "
        "{%0,%1,%2,%3}, {%4,%5,%6,%7}, {%8,%9}, {%0,%1,%2,%3};"
        : "+f"(c[0]), "+f"(c[1]), "+f"(c[2]), "+f"(c[3])
        : "r"(a[0]), "r"(a[1]), "r"(a[2]), "r"(a[3]), "r"(b0), "r"(b1));
}

// ---------------------------------------------------------------------------
// split_pack: fp32 [rows x 768] -> bf16 split [rows x 2304] stored as
// pre-swizzled 16KB tile blocks: block (mtile, kc) contiguous; within a block
// 128 rows x 128 bytes with SW128 swizzle (16B group g stored at g ^ (row&7)).
// lo_seg: which of the 3 K-segments carries the lo residual (2=act, 1=weight)
// ---------------------------------------------------------------------------
__global__ __launch_bounds__(256) void split_pack(
    const float* __restrict__ src, __nv_bfloat16* __restrict__ dst, int lo_seg)
{
    const int u   = blockIdx.x * 256 + threadIdx.x;
    const int g   = u % GROUPS_PER_ROW;
    const int m   = u / GROUPS_PER_ROW;
    const int kp0 = g * 8;
    const int seg = kp0 / DD;
    const int kk  = kp0 - seg * DD;
    const float* s = src + (size_t)m * DD + kk;

    __nv_bfloat16 vals[8];
    #pragma unroll
    for (int j = 0; j < 8; j++) {
        float v = s[j];
        __nv_bfloat16 hi = __float2bfloat16(v);
        vals[j] = (seg == lo_seg)
                ? __float2bfloat16(v - __bfloat162float(hi))
                : hi;
    }

    const int mtile = m >> 7, r = m & 127;
    const int kc = kp0 >> 6, c = kp0 & 63;
    const size_t base = ((size_t)mtile * NCHUNK + kc) * (size_t)TILE_BYTES;
    uint32_t off = (uint32_t)(r * 128 + c * 2);
    uint32_t sw  = off ^ ((off >> 3) & 0x70);      // group ^= row&7
    *reinterpret_cast<uint4*>(reinterpret_cast<char*>(dst) + base + sw) =
        *reinterpret_cast<const uint4*>(vals);
}

// ---------------------------------------------------------------------------
// bf16 mma.sync GEMM: C[m][n] = (sum A'[m][k']*W'[n][k'] + bias[n])*scale (+r)
// CTA 128x128, 8 warps (4M x 2N), warp 32x64, K'=2304 in 36 chunks of 64,
// cp.async double-buffered smem, ldmatrix + m16n8k16.
// ---------------------------------------------------------------------------
__global__ __launch_bounds__(256, 1)
void gemm_mma(const __nv_bfloat16* __restrict__ Ab,
              const __nv_bfloat16* __restrict__ Wb,
              const float* __restrict__ bias,
              const float* __restrict__ resid,
              float* __restrict__ C, float scale)
{
    extern __shared__ char dyn_smem[];
    const uint32_t sbase = (smem_u32(dyn_smem) + 127u) & ~127u;
    // layout: bufA0, bufW0, bufA1, bufW1 (16KB each)

    const int tid  = threadIdx.x;
    const int wid  = tid >> 5, lane = tid & 31;
    const int wm   = wid & 3, wn = wid >> 2;
    const int ntile = blockIdx.x, mtile = blockIdx.y;

    const char* Asrc = (const char*)Ab + (size_t)mtile * NCHUNK * TILE_BYTES;
    const char* Wsrc = (const char*)Wb + (size_t)ntile * NCHUNK * TILE_BYTES;

    float acc[2][8][4];
    #pragma unroll
    for (int mt = 0; mt < 2; mt++)
        #pragma unroll
        for (int nt = 0; nt < 8; nt++)
            #pragma unroll
            for (int j = 0; j < 4; j++) acc[mt][nt][j] = 0.0f;

    // prefetch helper: copy chunk i into buffer b
    auto prefetch = [&](int i, int b) {
        const uint32_t bufA = sbase + (uint32_t)b * (2 * TILE_BYTES);
        const uint32_t bufW = bufA + TILE_BYTES;
        const char* ga = Asrc + (size_t)i * TILE_BYTES;
        const char* gw = Wsrc + (size_t)i * TILE_BYTES;
        #pragma unroll
        for (int j = 0; j < 4; j++) {
            const uint32_t off = (uint32_t)(tid + j * 256) * 16;
            asm volatile("cp.async.cg.shared.global [%0], [%1], 16;"
                :: "r"(bufA + off), "l"(ga + off) : "memory");
            asm volatile("cp.async.cg.shared.global [%0], [%1], 16;"
                :: "r"(bufW + off), "l"(gw + off) : "memory");
        }
        asm volatile("cp.async.commit_group;" ::: "memory");
    };

    prefetch(0, 0);

    for (int i = 0; i < NCHUNK; i++) {
        if (i + 1 < NCHUNK) {
            prefetch(i + 1, (i + 1) & 1);
            asm volatile("cp.async.wait_group 1;" ::: "memory");
        } else {
            asm volatile("cp.async.wait_group 0;" ::: "memory");
        }
        __syncthreads();

        const uint32_t bufA = sbase + (uint32_t)(i & 1) * (2 * TILE_BYTES);
        const uint32_t bufW = bufA + TILE_BYTES;

        #pragma unroll
        for (int ks = 0; ks < 4; ks++) {
            uint32_t a[2][4];
            #pragma unroll
            for (int mt = 0; mt < 2; mt++) {
                const int r = wm * 32 + mt * 16 + (lane & 15);
                const int gr = ks * 2 + (lane >> 4);
                ldmx4(a[mt], bufA + r * 128 + ((gr ^ (r & 7)) << 4));
            }
            uint32_t b[4][4];
            #pragma unroll
            for (int np = 0; np < 4; np++) {
                const int r = wn * 64 + np * 16 + (lane & 7) + ((lane >> 4) << 3);
                const int gr = ks * 2 + ((lane >> 3) & 1);
                ldmx4(b[np], bufW + r * 128 + ((gr ^ (r & 7)) << 4));
            }
            #pragma unroll
            for (int mt = 0; mt < 2; mt++)
                #pragma unroll
                for (int nt = 0; nt < 8; nt++)
                    mma_bf16(acc[mt][nt], a[mt],
                             b[nt >> 1][(nt & 1) * 2],
                             b[nt >> 1][(nt & 1) * 2 + 1]);
        }
        __syncthreads();
    }

    // epilogue: fused bias/scale/residual
    const int row0 = mtile * MT + wm * 32;
    const int col0 = ntile * NT + wn * 64;
    #pragma unroll
    for (int mt = 0; mt < 2; mt++) {
        #pragma unroll
        for (int nt = 0; nt < 8; nt++) {
            const int r  = row0 + mt * 16 + (lane >> 2);
            const int cc = col0 + nt * 8 + (lane & 3) * 2;
            const float b0 = bias[cc], b1 = bias[cc + 1];
            float2 o0, o1;
            o0.x = (acc[mt][nt][0] + b0) * scale;
            o0.y = (acc[mt][nt][1] + b1) * scale;
            o1.x = (acc[mt][nt][2] + b0) * scale;
            o1.y = (acc[mt][nt][3] + b1) * scale;
            if (resid) {
                o0.x += resid[(size_t)r * DD + cc];
                o0.y += resid[(size_t)r * DD + cc + 1];
                o1.x += resid[(size_t)(r + 8) * DD + cc];
                o1.y += resid[(size_t)(r + 8) * DD + cc + 1];
            }
            *reinterpret_cast<float2*>(C + (size_t)r * DD + cc)       = o0;
            *reinterpret_cast<float2*>(C + (size_t)(r + 8) * DD + cc) = o1;
        }
    }
}

// ---------------------------------------------------------------------------
// graph / softmax / message-passing kernels (unchanged from passing round 2)
// ---------------------------------------------------------------------------
__device__ __forceinline__ void atomicMaxFloat(float* addr, float val) {
    if (val >= 0.0f) atomicMax((int*)addr, __float_as_int(val));
    else             atomicMin((unsigned int*)addr, __float_as_uint(val));
}

__global__ void init_kernel() {
    int i = blockIdx.x * blockDim.x + threadIdx.x;
    if (i < NN * HH) { g_smax[i] = -3.0e38f; g_denom[i] = 0.0f; }
    if (i < NN) g_cnt[i] = 0;
}

__global__ void count_kernel(const int* __restrict__ dst) {
    int e = blockIdx.x * blockDim.x + threadIdx.x;
    if (e < EE) atomicAdd(&g_cnt[dst[e]], 1);
}

__global__ __launch_bounds__(1024) void scan_kernel() {
    __shared__ int ssum[1024];
    const int t = threadIdx.x;
    const int base = t * 8;
    int local[8];
    int s = 0;
    #pragma unroll
    for (int i = 0; i < 8; i++) { local[i] = g_cnt[base + i]; s += local[i]; }
    ssum[t] = s;
    __syncthreads();
    for (int off = 1; off < 1024; off <<= 1) {
        int v = (t >= off) ? ssum[t - off] : 0;
        __syncthreads();
        ssum[t] += v;
        __syncthreads();
    }
    int pre = (t == 0) ? 0 : ssum[t - 1];
    #pragma unroll
    for (int i = 0; i < 8; i++) {
        g_rowptr[base + i] = pre;
        pre += local[i];
        g_cnt[base + i] = 0;
    }
    if (t == 1023) g_rowptr[NN] = pre;
}

__global__ void scatter_kernel(const int* __restrict__ src,
                               const int* __restrict__ dst) {
    int e = blockIdx.x * blockDim.x + threadIdx.x;
    if (e < EE) {
        int d = dst[e];
        int pos = g_rowptr[d] + atomicAdd(&g_cnt[d], 1);
        g_pos[e] = pos;
        g_csr_src[pos] = src[e];
    }
}

__global__ __launch_bounds__(256) void score_kernel(
    const int* __restrict__ src, const int* __restrict__ dst,
    const float* __restrict__ am)
{
    const int gw   = (blockIdx.x * blockDim.x + threadIdx.x) >> 5;
    const int lane = threadIdx.x & 31;
    if (gw >= EE) return;
    const int s = src[gw];
    const int d = dst[gw];
    const float* kr = g_k + (size_t)s * DD;
    const float* qr = g_q + (size_t)d * DD;
    const bool m = (am[d] >= 0.0f);

    #pragma unroll
    for (int h = 0; h < HH; h++) {
        const int i0 = h * HDIM + lane;
        float p = kr[i0] * qr[i0] + kr[i0 + 32] * qr[i0 + 32];
        #pragma unroll
        for (int off = 16; off; off >>= 1)
            p += __shfl_xor_sync(0xFFFFFFFFu, p, off);
        if (lane == 0) {
            float sc = m ? p : -1.0e4f;
            g_score[gw * HH + h] = sc;
            atomicMaxFloat(&g_smax[d * HH + h], sc);
        }
    }
}

__global__ void exp_kernel(const int* __restrict__ dst) {
    int i = blockIdx.x * blockDim.x + threadIdx.x;
    if (i < EE * HH) {
        int e = i / HH;
        int h = i - e * HH;
        int d = dst[e];
        float p = __expf(g_score[i] - g_smax[d * HH + h]);
        g_score[i] = p;
        atomicAdd(&g_denom[d * HH + h], p);
    }
}

__global__ void attn_kernel(const int* __restrict__ dst) {
    int i = blockIdx.x * blockDim.x + threadIdx.x;
    if (i < EE * HH) {
        int e = i / HH;
        int h = i - e * HH;
        int d = dst[e];
        g_csr_attn[(size_t)g_pos[e] * HH + h] = g_score[i] / g_denom[d * HH + h];
    }
}

#define CHUNK 32
__global__ __launch_bounds__(256) void agg_kernel(
    const float* __restrict__ hin, float* __restrict__ hout)
{
    const int node = blockIdx.x;
    const int t    = threadIdx.x;
    const int beg  = g_rowptr[node];
    const int end  = g_rowptr[node + 1];

    const int h0 = t >> 6;
    const int h1 = (t + 256) >> 6;
    const int h2 = (t + 512) >> 6;

    float a0 = 0.0f, a1 = 0.0f, a2 = 0.0f;

    __shared__ int   s_src[CHUNK];
    __shared__ float s_attn[CHUNK * HH];

    for (int cs = beg; cs < end; cs += CHUNK) {
        const int c = min(CHUNK, end - cs);
        __syncthreads();
        if (t < c) s_src[t] = g_csr_src[cs + t];
        for (int i = t; i < c * HH; i += 256)
            s_attn[i] = g_csr_attn[(size_t)cs * HH + i];
        __syncthreads();
        #pragma unroll 4
        for (int j = 0; j < c; j++) {
            const float* hr = hin + (size_t)s_src[j] * DD;
            a0 += s_attn[j * HH + h0] * hr[t];
            a1 += s_attn[j * HH + h1] * hr[t + 256];
            a2 += s_attn[j * HH + h2] * hr[t + 512];
        }
    }

    const size_t base = (size_t)node * DD;
    hout[base + t]       = 0.9f * a0 + 0.1f * g_v[base + t];
    hout[base + t + 256] = 0.9f * a1 + 0.1f * g_v[base + t + 256];
    hout[base + t + 512] = 0.9f * a2 + 0.1f * g_v[base + t + 512];
}

__global__ __launch_bounds__(256) void ln_kernel(
    const float* __restrict__ y, const float* __restrict__ gamma,
    const float* __restrict__ beta, float* __restrict__ out)
{
    const int row = blockIdx.x;
    const int t   = threadIdx.x;
    const size_t base = (size_t)row * DD;

    const float x0 = y[base + t];
    const float x1 = y[base + t + 256];
    const float x2 = y[base + t + 512];

    __shared__ float sdata[256];
    sdata[t] = x0 + x1 + x2;
    __syncthreads();
    for (int off = 128; off > 0; off >>= 1) {
        if (t < off) sdata[t] += sdata[t + off];
        __syncthreads();
    }
    const float mu = sdata[0] * (1.0f / DD);
    __syncthreads();

    const float d0 = x0 - mu, d1 = x1 - mu, d2 = x2 - mu;
    sdata[t] = d0 * d0 + d1 * d1 + d2 * d2;
    __syncthreads();
    for (int off = 128; off > 0; off >>= 1) {
        if (t < off) sdata[t] += sdata[t + off];
        __syncthreads();
    }
    const float inv = rsqrtf(sdata[0] * (1.0f / DD) + 1e-12f);

    out[base + t]       = d0 * inv * gamma[t]       + beta[t];
    out[base + t + 256] = d1 * inv * gamma[t + 256] + beta[t + 256];
    out[base + t + 512] = d2 * inv * gamma[t + 512] + beta[t + 512];
}

// ---------------------------------------------------------------------------
// launch
// ---------------------------------------------------------------------------
static float* symF(const void* sym) {
    void* p = nullptr;
    cudaGetSymbolAddress(&p, sym);
    return (float*)p;
}
static __nv_bfloat16* symB(const void* sym) {
    void* p = nullptr;
    cudaGetSymbolAddress(&p, sym);
    return (__nv_bfloat16*)p;
}

#define GEMM_SMEM (4 * TILE_BYTES + 128)

extern "C" void kernel_launch(void* const* d_in, const int* in_sizes, int n_in,
                              void* d_out, int out_size) {
    const float* x    = (const float*)d_in[0];
    const float* am   = (const float*)d_in[1];
    const int*   esrc = (const int*)d_in[2];
    const int*   edst = (const int*)d_in[3];
    const float* Wq   = (const float*)d_in[4];
    const float* bq   = (const float*)d_in[5];
    const float* Wk   = (const float*)d_in[6];
    const float* bk   = (const float*)d_in[7];
    const float* Wv   = (const float*)d_in[8];
    const float* bv   = (const float*)d_in[9];
    const float* Wo   = (const float*)d_in[10];
    const float* bo   = (const float*)d_in[11];
    const float* lng  = (const float*)d_in[12];
    const float* lnb  = (const float*)d_in[13];
    float* out = (float*)d_out;

    float* q  = symF(g_q);
    float* k  = symF(g_k);
    float* v  = symF(g_v);
    float* ha = symF(g_ha);
    float* hb = symF(g_hb);
    float* y  = symF(g_y);

    __nv_bfloat16* ax  = symB(g_ax);
    __nv_bfloat16* ah  = symB(g_ah);
    __nv_bfloat16* wqs = symB(g_wqs);
    __nv_bfloat16* wks = symB(g_wks);
    __nv_bfloat16* wvs = symB(g_wvs);
    __nv_bfloat16* wos = symB(g_wos);

    cudaFuncSetAttribute(gemm_mma, cudaFuncAttributeMaxDynamicSharedMemorySize,
                         GEMM_SMEM);

    const int ACT_BLKS = (NN * GROUPS_PER_ROW) / 256;   // 9216
    const int W_BLKS   = (DD * GROUPS_PER_ROW) / 256;   // 864
    const dim3 gemm_grid(DD / NT, NN / MT);             // (6, 64)

    // pack activations and weights into split-bf16 swizzled tile blocks
    split_pack<<<ACT_BLKS, 256>>>(x,  ax,  2);
    split_pack<<<W_BLKS,   256>>>(Wq, wqs, 1);
    split_pack<<<W_BLKS,   256>>>(Wk, wks, 1);
    split_pack<<<W_BLKS,   256>>>(Wv, wvs, 1);
    split_pack<<<W_BLKS,   256>>>(Wo, wos, 1);

    // q/k/v projections on tensor cores (q scaled by 1/sqrt(64) after bias)
    gemm_mma<<<gemm_grid, 256, GEMM_SMEM>>>(ax, wqs, bq, nullptr, q, 0.125f);
    gemm_mma<<<gemm_grid, 256, GEMM_SMEM>>>(ax, wks, bk, nullptr, k, 1.0f);
    gemm_mma<<<gemm_grid, 256, GEMM_SMEM>>>(ax, wvs, bv, nullptr, v, 1.0f);

    // CSR build + softmax state init
    init_kernel<<<(NN * HH + 255) / 256, 256>>>();
    count_kernel<<<(EE + 255) / 256, 256>>>(edst);
    scan_kernel<<<1, 1024>>>();
    scatter_kernel<<<(EE + 255) / 256, 256>>>(esrc, edst);

    // edge scores + softmax (attn written in CSR order)
    score_kernel<<<(EE * 32) / 256, 256>>>(esrc, edst, am);
    exp_kernel<<<(EE * HH + 255) / 256, 256>>>(edst);
    attn_kernel<<<(EE * HH + 255) / 256, 256>>>(edst);

    // 5 message-passing steps
    agg_kernel<<<NN, 256>>>(v,  ha);
    agg_kernel<<<NN, 256>>>(ha, hb);
    agg_kernel<<<NN, 256>>>(hb, ha);
    agg_kernel<<<NN, 256>>>(ha, hb);
    agg_kernel<<<NN, 256>>>(hb, ha);

    // output projection (+x residual) on tensor cores, then LayerNorm
    split_pack<<<ACT_BLKS, 256>>>(ha, ah, 2);
    gemm_mma<<<gemm_grid, 256, GEMM_SMEM>>>(ah, wos, bo, x, y, 1.0f);
    ln_kernel<<<NN, 256>>>(y, lng, lnb, out);
}

// round 5
// speedup vs baseline: 2.3216x; 1.1595x over previous
#include <cuda_runtime.h>
#include <cuda_bf16.h>
#include <cstdint>

// ---------------------------------------------------------------------------
// Problem constants
// ---------------------------------------------------------------------------
#define NN    8192          // B*S nodes
#define DD    768           // hidden dim
#define HH    12            // heads
#define HDIM  64            // head dim
#define EE    131072        // edges

// split-bf16 GEMM constants
#define KSPLIT 2304         // 3*DD (hi|hi|lo vs hi|lo|hi)
#define NCHUNK 36           // KSPLIT/64
#define MT     128          // M tile
#define NT     128          // N tile
#define TILE_BYTES 16384    // 128 rows * 128 bytes
#define GROUPS_PER_ROW (KSPLIT/8)   // 288 16B-units per row

// ---------------------------------------------------------------------------
// Scratch (static device globals — no allocation allowed)
// ---------------------------------------------------------------------------
__device__ float g_q[NN * DD];
__device__ float g_k[NN * DD];
__device__ float g_v[NN * DD];
__device__ float g_ha[NN * DD];
__device__ float g_hb[NN * DD];
__device__ float g_y[NN * DD];

__device__ int   g_cnt[NN];
__device__ int   g_rowptr[NN + 1];
__device__ int   g_csr_src[EE];          // src node per CSR slot
__device__ float g_csr_attn[EE * HH];    // scores then normalized attn (CSR order)

// split-bf16 operand storage (pre-swizzled 16KB tile blocks)
__device__ __align__(128) __nv_bfloat16 g_ax[(size_t)NN * KSPLIT];   // x  split
__device__ __align__(128) __nv_bfloat16 g_ah[(size_t)NN * KSPLIT];   // h  split
__device__ __align__(128) __nv_bfloat16 g_wqs[(size_t)DD * KSPLIT];
__device__ __align__(128) __nv_bfloat16 g_wks[(size_t)DD * KSPLIT];
__device__ __align__(128) __nv_bfloat16 g_wvs[(size_t)DD * KSPLIT];
__device__ __align__(128) __nv_bfloat16 g_wos[(size_t)DD * KSPLIT];

// ---------------------------------------------------------------------------
// helpers
// ---------------------------------------------------------------------------
__device__ __forceinline__ uint32_t smem_u32(const void* p) {
    uint32_t a;
    asm("{ .reg .u64 t; cvta.to.shared.u64 t, %1; cvt.u32.u64 %0, t; }"
        : "=r"(a) : "l"(p));
    return a;
}

__device__ __forceinline__ void ldmx4(uint32_t* r, uint32_t addr) {
    asm volatile("ldmatrix.sync.aligned.m8n8.x4.shared.b16 {%0,%1,%2,%3}, [%4];"
        : "=r"(r[0]), "=r"(r[1]), "=r"(r[2]), "=r"(r[3]) : "r"(addr));
}

__device__ __forceinline__ void mma_bf16(float* c, const uint32_t* a,
                                         uint32_t b0, uint32_t b1) {
    asm volatile(
        "mma.sync.aligned.m16n8k16.row.col.f32.bf16.bf16.f32 "
        "{%0,%1,%2,%3}, {%4,%5,%6,%7}, {%8,%9}, {%0,%1,%2,%3};"
        : "+f"(c[0]), "+f"(c[1]), "+f"(c[2]), "+f"(c[3])
        : "r"(a[0]), "r"(a[1]), "r"(a[2]), "r"(a[3]), "r"(b0), "r"(b1));
}

// ---------------------------------------------------------------------------
// split_pack: fp32 [rows x 768] -> bf16 split [rows x 2304] stored as
// pre-swizzled 16KB tile blocks (SW128: 16B group g stored at g ^ (row&7)).
// lo_seg: which of the 3 K-segments carries the lo residual (2=act, 1=weight)
// ---------------------------------------------------------------------------
__global__ __launch_bounds__(256) void split_pack(
    const float* __restrict__ src, __nv_bfloat16* __restrict__ dst, int lo_seg)
{
    const int u   = blockIdx.x * 256 + threadIdx.x;
    const int g   = u % GROUPS_PER_ROW;
    const int m   = u / GROUPS_PER_ROW;
    const int kp0 = g * 8;
    const int seg = kp0 / DD;
    const int kk  = kp0 - seg * DD;
    const float* s = src + (size_t)m * DD + kk;

    __nv_bfloat16 vals[8];
    #pragma unroll
    for (int j = 0; j < 8; j++) {
        float v = s[j];
        __nv_bfloat16 hi = __float2bfloat16(v);
        vals[j] = (seg == lo_seg)
                ? __float2bfloat16(v - __bfloat162float(hi))
                : hi;
    }

    const int mtile = m >> 7, r = m & 127;
    const int kc = kp0 >> 6, c = kp0 & 63;
    const size_t base = ((size_t)mtile * NCHUNK + kc) * (size_t)TILE_BYTES;
    uint32_t off = (uint32_t)(r * 128 + c * 2);
    uint32_t sw  = off ^ ((off >> 3) & 0x70);
    *reinterpret_cast<uint4*>(reinterpret_cast<char*>(dst) + base + sw) =
        *reinterpret_cast<const uint4*>(vals);
}

// ---------------------------------------------------------------------------
// bf16 mma.sync GEMM (unchanged from round 4): CTA 128x128, 8 warps (4Mx2N),
// K'=2304 in 36 chunks of 64, cp.async double-buffered, ldmatrix+m16n8k16.
// ---------------------------------------------------------------------------
__global__ __launch_bounds__(256, 1)
void gemm_mma(const __nv_bfloat16* __restrict__ Ab,
              const __nv_bfloat16* __restrict__ Wb,
              const float* __restrict__ bias,
              const float* __restrict__ resid,
              float* __restrict__ C, float scale)
{
    extern __shared__ char dyn_smem[];
    const uint32_t sbase = (smem_u32(dyn_smem) + 127u) & ~127u;

    const int tid  = threadIdx.x;
    const int wid  = tid >> 5, lane = tid & 31;
    const int wm   = wid & 3, wn = wid >> 2;
    const int ntile = blockIdx.x, mtile = blockIdx.y;

    const char* Asrc = (const char*)Ab + (size_t)mtile * NCHUNK * TILE_BYTES;
    const char* Wsrc = (const char*)Wb + (size_t)ntile * NCHUNK * TILE_BYTES;

    float acc[2][8][4];
    #pragma unroll
    for (int mt = 0; mt < 2; mt++)
        #pragma unroll
        for (int nt = 0; nt < 8; nt++)
            #pragma unroll
            for (int j = 0; j < 4; j++) acc[mt][nt][j] = 0.0f;

    auto prefetch = [&](int i, int b) {
        const uint32_t bufA = sbase + (uint32_t)b * (2 * TILE_BYTES);
        const uint32_t bufW = bufA + TILE_BYTES;
        const char* ga = Asrc + (size_t)i * TILE_BYTES;
        const char* gw = Wsrc + (size_t)i * TILE_BYTES;
        #pragma unroll
        for (int j = 0; j < 4; j++) {
            const uint32_t off = (uint32_t)(tid + j * 256) * 16;
            asm volatile("cp.async.cg.shared.global [%0], [%1], 16;"
                :: "r"(bufA + off), "l"(ga + off) : "memory");
            asm volatile("cp.async.cg.shared.global [%0], [%1], 16;"
                :: "r"(bufW + off), "l"(gw + off) : "memory");
        }
        asm volatile("cp.async.commit_group;" ::: "memory");
    };

    prefetch(0, 0);

    for (int i = 0; i < NCHUNK; i++) {
        if (i + 1 < NCHUNK) {
            prefetch(i + 1, (i + 1) & 1);
            asm volatile("cp.async.wait_group 1;" ::: "memory");
        } else {
            asm volatile("cp.async.wait_group 0;" ::: "memory");
        }
        __syncthreads();

        const uint32_t bufA = sbase + (uint32_t)(i & 1) * (2 * TILE_BYTES);
        const uint32_t bufW = bufA + TILE_BYTES;

        #pragma unroll
        for (int ks = 0; ks < 4; ks++) {
            uint32_t a[2][4];
            #pragma unroll
            for (int mt = 0; mt < 2; mt++) {
                const int r = wm * 32 + mt * 16 + (lane & 15);
                const int gr = ks * 2 + (lane >> 4);
                ldmx4(a[mt], bufA + r * 128 + ((gr ^ (r & 7)) << 4));
            }
            uint32_t b[4][4];
            #pragma unroll
            for (int np = 0; np < 4; np++) {
                const int r = wn * 64 + np * 16 + (lane & 7) + ((lane >> 4) << 3);
                const int gr = ks * 2 + ((lane >> 3) & 1);
                ldmx4(b[np], bufW + r * 128 + ((gr ^ (r & 7)) << 4));
            }
            #pragma unroll
            for (int mt = 0; mt < 2; mt++)
                #pragma unroll
                for (int nt = 0; nt < 8; nt++)
                    mma_bf16(acc[mt][nt], a[mt],
                             b[nt >> 1][(nt & 1) * 2],
                             b[nt >> 1][(nt & 1) * 2 + 1]);
        }
        __syncthreads();
    }

    const int row0 = mtile * MT + wm * 32;
    const int col0 = ntile * NT + wn * 64;
    #pragma unroll
    for (int mt = 0; mt < 2; mt++) {
        #pragma unroll
        for (int nt = 0; nt < 8; nt++) {
            const int r  = row0 + mt * 16 + (lane >> 2);
            const int cc = col0 + nt * 8 + (lane & 3) * 2;
            const float b0 = bias[cc], b1 = bias[cc + 1];
            float2 o0, o1;
            o0.x = (acc[mt][nt][0] + b0) * scale;
            o0.y = (acc[mt][nt][1] + b1) * scale;
            o1.x = (acc[mt][nt][2] + b0) * scale;
            o1.y = (acc[mt][nt][3] + b1) * scale;
            if (resid) {
                o0.x += resid[(size_t)r * DD + cc];
                o0.y += resid[(size_t)r * DD + cc + 1];
                o1.x += resid[(size_t)(r + 8) * DD + cc];
                o1.y += resid[(size_t)(r + 8) * DD + cc + 1];
            }
            *reinterpret_cast<float2*>(C + (size_t)r * DD + cc)       = o0;
            *reinterpret_cast<float2*>(C + (size_t)(r + 8) * DD + cc) = o1;
        }
    }
}

// ---------------------------------------------------------------------------
// CSR build
// ---------------------------------------------------------------------------
__global__ void init_cnt() {
    int i = blockIdx.x * blockDim.x + threadIdx.x;
    if (i < NN) g_cnt[i] = 0;
}

__global__ void count_kernel(const int* __restrict__ dst) {
    int e = blockIdx.x * blockDim.x + threadIdx.x;
    if (e < EE) atomicAdd(&g_cnt[dst[e]], 1);
}

__global__ __launch_bounds__(1024) void scan_kernel() {
    __shared__ int ssum[1024];
    const int t = threadIdx.x;
    const int base = t * 8;
    int local[8];
    int s = 0;
    #pragma unroll
    for (int i = 0; i < 8; i++) { local[i] = g_cnt[base + i]; s += local[i]; }
    ssum[t] = s;
    __syncthreads();
    for (int off = 1; off < 1024; off <<= 1) {
        int v = (t >= off) ? ssum[t - off] : 0;
        __syncthreads();
        ssum[t] += v;
        __syncthreads();
    }
    int pre = (t == 0) ? 0 : ssum[t - 1];
    #pragma unroll
    for (int i = 0; i < 8; i++) {
        g_rowptr[base + i] = pre;
        pre += local[i];
        g_cnt[base + i] = 0;
    }
    if (t == 1023) g_rowptr[NN] = pre;
}

__global__ void scatter_kernel(const int* __restrict__ src,
                               const int* __restrict__ dst) {
    int e = blockIdx.x * blockDim.x + threadIdx.x;
    if (e < EE) {
        int d = dst[e];
        int pos = g_rowptr[d] + atomicAdd(&g_cnt[d], 1);
        g_csr_src[pos] = src[e];
    }
}

// ---------------------------------------------------------------------------
// score_csr: block per dst node. q row staged in smem once; warps iterate the
// node's CSR slots; raw (masked) scores written to g_csr_attn in CSR order.
// ---------------------------------------------------------------------------
__global__ __launch_bounds__(256) void score_csr(const float* __restrict__ am) {
    __shared__ float qs[DD];
    const int node = blockIdx.x;
    const int t    = threadIdx.x;
    const int wid  = t >> 5, lane = t & 31;

    qs[t]       = g_q[(size_t)node * DD + t];
    qs[t + 256] = g_q[(size_t)node * DD + t + 256];
    qs[t + 512] = g_q[(size_t)node * DD + t + 512];
    const bool m = (am[node] >= 0.0f);
    __syncthreads();

    const int beg = g_rowptr[node], end = g_rowptr[node + 1];
    for (int slot = beg + wid; slot < end; slot += 8) {
        const float* kr = g_k + (size_t)g_csr_src[slot] * DD;
        float myscore = 0.0f;
        #pragma unroll
        for (int h = 0; h < HH; h++) {
            const int i0 = h * HDIM + lane;
            float p = kr[i0] * qs[i0] + kr[i0 + 32] * qs[i0 + 32];
            #pragma unroll
            for (int off = 16; off; off >>= 1)
                p += __shfl_xor_sync(0xFFFFFFFFu, p, off);
            if (lane == h) myscore = m ? p : -1.0e4f;
        }
        if (lane < HH) g_csr_attn[(size_t)slot * HH + lane] = myscore;
    }
}

// ---------------------------------------------------------------------------
// softmax_csr: one warp per node, lane = head. Normalizes the node's CSR
// segment of g_csr_attn in place (max, exp+sum, scale).
// ---------------------------------------------------------------------------
__global__ __launch_bounds__(256) void softmax_csr() {
    const int node = blockIdx.x * 8 + (threadIdx.x >> 5);
    const int lane = threadIdx.x & 31;
    if (lane >= HH) return;
    const int beg = g_rowptr[node], end = g_rowptr[node + 1];

    float mx = -3.0e38f;
    for (int s = beg; s < end; s++)
        mx = fmaxf(mx, g_csr_attn[(size_t)s * HH + lane]);
    float sum = 0.0f;
    for (int s = beg; s < end; s++) {
        float p = __expf(g_csr_attn[(size_t)s * HH + lane] - mx);
        g_csr_attn[(size_t)s * HH + lane] = p;
        sum += p;
    }
    const float inv = 1.0f / sum;
    for (int s = beg; s < end; s++)
        g_csr_attn[(size_t)s * HH + lane] *= inv;
}

// ---------------------------------------------------------------------------
// agg: hout[n] = 0.9 * sum attn*h[src] + 0.1 * v[n].  192 thr, float4/thread.
// Last step (dst_split != null) writes the bf16 split tiles directly.
// ---------------------------------------------------------------------------
__global__ __launch_bounds__(192) void agg_kernel(
    const float* __restrict__ hin, float* __restrict__ hout,
    __nv_bfloat16* __restrict__ dst_split)
{
    const int node = blockIdx.x;
    const int t    = threadIdx.x;
    const int beg  = g_rowptr[node], end = g_rowptr[node + 1];
    const int head = t >> 4;           // 4t / 64
    const int col  = t * 4;

    float4 acc = {0.0f, 0.0f, 0.0f, 0.0f};

    __shared__ int   s_src[32];
    __shared__ float s_attn[32 * HH];

    for (int cs = beg; cs < end; cs += 32) {
        const int c = min(32, end - cs);
        __syncthreads();
        if (t < c) s_src[t] = g_csr_src[cs + t];
        for (int i = t; i < c * HH; i += 192)
            s_attn[i] = g_csr_attn[(size_t)cs * HH + i];
        __syncthreads();
        #pragma unroll 4
        for (int j = 0; j < c; j++) {
            const float4 hv = *reinterpret_cast<const float4*>(
                hin + (size_t)s_src[j] * DD + col);
            const float w = s_attn[j * HH + head];
            acc.x += w * hv.x; acc.y += w * hv.y;
            acc.z += w * hv.z; acc.w += w * hv.w;
        }
    }

    const float4 vv = *reinterpret_cast<const float4*>(
        g_v + (size_t)node * DD + col);
    float4 o;
    o.x = 0.9f * acc.x + 0.1f * vv.x;
    o.y = 0.9f * acc.y + 0.1f * vv.y;
    o.z = 0.9f * acc.z + 0.1f * vv.z;
    o.w = 0.9f * acc.w + 0.1f * vv.w;

    if (dst_split) {
        float vals[4] = {o.x, o.y, o.z, o.w};
        __align__(8) __nv_bfloat16 hi[4], lo[4];
        #pragma unroll
        for (int j = 0; j < 4; j++) {
            hi[j] = __float2bfloat16(vals[j]);
            lo[j] = __float2bfloat16(vals[j] - __bfloat162float(hi[j]));
        }
        const int mtile = node >> 7, r = node & 127;
        #pragma unroll
        for (int seg = 0; seg < 3; seg++) {
            const int kp = col + seg * DD;
            const int kc = kp >> 6, cc = kp & 63;
            const size_t base = ((size_t)mtile * NCHUNK + kc) * (size_t)TILE_BYTES;
            uint32_t off = (uint32_t)(r * 128 + cc * 2);
            uint32_t sw  = off ^ ((off >> 3) & 0x70);
            *reinterpret_cast<uint2*>(reinterpret_cast<char*>(dst_split) + base + sw) =
                *reinterpret_cast<const uint2*>(seg == 2 ? lo : hi);
        }
    } else {
        *reinterpret_cast<float4*>(hout + (size_t)node * DD + col) = o;
    }
}

// ---------------------------------------------------------------------------
// LayerNorm: block per row, 256 thr x 3 dims
// ---------------------------------------------------------------------------
__global__ __launch_bounds__(256) void ln_kernel(
    const float* __restrict__ y, const float* __restrict__ gamma,
    const float* __restrict__ beta, float* __restrict__ out)
{
    const int row = blockIdx.x;
    const int t   = threadIdx.x;
    const size_t base = (size_t)row * DD;

    const float x0 = y[base + t];
    const float x1 = y[base + t + 256];
    const float x2 = y[base + t + 512];

    __shared__ float sdata[256];
    sdata[t] = x0 + x1 + x2;
    __syncthreads();
    for (int off = 128; off > 0; off >>= 1) {
        if (t < off) sdata[t] += sdata[t + off];
        __syncthreads();
    }
    const float mu = sdata[0] * (1.0f / DD);
    __syncthreads();

    const float d0 = x0 - mu, d1 = x1 - mu, d2 = x2 - mu;
    sdata[t] = d0 * d0 + d1 * d1 + d2 * d2;
    __syncthreads();
    for (int off = 128; off > 0; off >>= 1) {
        if (t < off) sdata[t] += sdata[t + off];
        __syncthreads();
    }
    const float inv = rsqrtf(sdata[0] * (1.0f / DD) + 1e-12f);

    out[base + t]       = d0 * inv * gamma[t]       + beta[t];
    out[base + t + 256] = d1 * inv * gamma[t + 256] + beta[t + 256];
    out[base + t + 512] = d2 * inv * gamma[t + 512] + beta[t + 512];
}

// ---------------------------------------------------------------------------
// launch
// ---------------------------------------------------------------------------
static float* symF(const void* sym) {
    void* p = nullptr;
    cudaGetSymbolAddress(&p, sym);
    return (float*)p;
}
static __nv_bfloat16* symB(const void* sym) {
    void* p = nullptr;
    cudaGetSymbolAddress(&p, sym);
    return (__nv_bfloat16*)p;
}

#define GEMM_SMEM (4 * TILE_BYTES + 128)

extern "C" void kernel_launch(void* const* d_in, const int* in_sizes, int n_in,
                              void* d_out, int out_size) {
    const float* x    = (const float*)d_in[0];
    const float* am   = (const float*)d_in[1];
    const int*   esrc = (const int*)d_in[2];
    const int*   edst = (const int*)d_in[3];
    const float* Wq   = (const float*)d_in[4];
    const float* bq   = (const float*)d_in[5];
    const float* Wk   = (const float*)d_in[6];
    const float* bk   = (const float*)d_in[7];
    const float* Wv   = (const float*)d_in[8];
    const float* bv   = (const float*)d_in[9];
    const float* Wo   = (const float*)d_in[10];
    const float* bo   = (const float*)d_in[11];
    const float* lng  = (const float*)d_in[12];
    const float* lnb  = (const float*)d_in[13];
    float* out = (float*)d_out;

    float* q  = symF(g_q);
    float* k  = symF(g_k);
    float* v  = symF(g_v);
    float* ha = symF(g_ha);
    float* hb = symF(g_hb);
    float* y  = symF(g_y);

    __nv_bfloat16* ax  = symB(g_ax);
    __nv_bfloat16* ah  = symB(g_ah);
    __nv_bfloat16* wqs = symB(g_wqs);
    __nv_bfloat16* wks = symB(g_wks);
    __nv_bfloat16* wvs = symB(g_wvs);
    __nv_bfloat16* wos = symB(g_wos);

    cudaFuncSetAttribute(gemm_mma, cudaFuncAttributeMaxDynamicSharedMemorySize,
                         GEMM_SMEM);

    const int ACT_BLKS = (NN * GROUPS_PER_ROW) / 256;   // 9216
    const int W_BLKS   = (DD * GROUPS_PER_ROW) / 256;   // 864
    const dim3 gemm_grid(DD / NT, NN / MT);             // (6, 64)

    // pack activations and weights into split-bf16 swizzled tile blocks
    split_pack<<<ACT_BLKS, 256>>>(x,  ax,  2);
    split_pack<<<W_BLKS,   256>>>(Wq, wqs, 1);
    split_pack<<<W_BLKS,   256>>>(Wk, wks, 1);
    split_pack<<<W_BLKS,   256>>>(Wv, wvs, 1);
    split_pack<<<W_BLKS,   256>>>(Wo, wos, 1);

    // q/k/v projections on tensor cores (q scaled by 1/sqrt(64) after bias)
    gemm_mma<<<gemm_grid, 256, GEMM_SMEM>>>(ax, wqs, bq, nullptr, q, 0.125f);
    gemm_mma<<<gemm_grid, 256, GEMM_SMEM>>>(ax, wks, bk, nullptr, k, 1.0f);
    gemm_mma<<<gemm_grid, 256, GEMM_SMEM>>>(ax, wvs, bv, nullptr, v, 1.0f);

    // CSR build
    init_cnt<<<NN / 256, 256>>>();
    count_kernel<<<(EE + 255) / 256, 256>>>(edst);
    scan_kernel<<<1, 1024>>>();
    scatter_kernel<<<(EE + 255) / 256, 256>>>(esrc, edst);

    // fused CSR-order scores + per-node softmax (no atomics, no scatter)
    score_csr<<<NN, 256>>>(am);
    softmax_csr<<<NN / 8, 256>>>();

    // 5 message-passing steps; last one writes the bf16 split tiles directly
    agg_kernel<<<NN, 192>>>(v,  ha, nullptr);
    agg_kernel<<<NN, 192>>>(ha, hb, nullptr);
    agg_kernel<<<NN, 192>>>(hb, ha, nullptr);
    agg_kernel<<<NN, 192>>>(ha, hb, nullptr);
    agg_kernel<<<NN, 192>>>(hb, nullptr, ah);

    // output projection (+x residual) on tensor cores, then LayerNorm
    gemm_mma<<<gemm_grid, 256, GEMM_SMEM>>>(ah, wos, bo, x, y, 1.0f);
    ln_kernel<<<NN, 256>>>(y, lng, lnb, out);
}

// round 6
// speedup vs baseline: 2.4640x; 1.0613x over previous
#include <cuda_runtime.h>
#include <cuda_bf16.h>
#include <cstdint>

// ---------------------------------------------------------------------------
// Problem constants
// ---------------------------------------------------------------------------
#define NN    8192          // B*S nodes
#define DD    768           // hidden dim
#define HH    12            // heads
#define HDIM  64            // head dim
#define EE    131072        // edges

// split-bf16 GEMM constants
#define KSPLIT 2304         // 3*DD (hi|hi|lo vs hi|lo|hi)
#define NCHUNK 36           // KSPLIT/64
#define MT     128          // M tile
#define NT     128          // N tile
#define TILE_BYTES 16384    // 128 rows * 128 bytes
#define GROUPS_PER_ROW (KSPLIT/8)   // 288 16B-units per row
#define NSTAGE 4
#define GEMM_SMEM (NSTAGE * 2 * TILE_BYTES + 128)   // 128KB + pad

// ---------------------------------------------------------------------------
// Scratch (static device globals — no allocation allowed)
// ---------------------------------------------------------------------------
__device__ float g_q[NN * DD];
__device__ float g_k[NN * DD];
__device__ float g_v[NN * DD];
__device__ float g_ha[NN * DD];
__device__ float g_hb[NN * DD];
__device__ float g_y[NN * DD];

__device__ int   g_cnt[NN];
__device__ int   g_rowptr[NN + 1];
__device__ int   g_csr_src[EE];          // src node per CSR slot
__device__ float g_csr_attn[EE * HH];    // scores then normalized attn (CSR order)

// split-bf16 operand storage (pre-swizzled 16KB tile blocks)
__device__ __align__(128) __nv_bfloat16 g_ax[(size_t)NN * KSPLIT];   // x  split
__device__ __align__(128) __nv_bfloat16 g_ah[(size_t)NN * KSPLIT];   // h  split
__device__ __align__(128) __nv_bfloat16 g_wqs[(size_t)DD * KSPLIT];
__device__ __align__(128) __nv_bfloat16 g_wks[(size_t)DD * KSPLIT];
__device__ __align__(128) __nv_bfloat16 g_wvs[(size_t)DD * KSPLIT];
__device__ __align__(128) __nv_bfloat16 g_wos[(size_t)DD * KSPLIT];

// ---------------------------------------------------------------------------
// helpers
// ---------------------------------------------------------------------------
__device__ __forceinline__ uint32_t smem_u32(const void* p) {
    uint32_t a;
    asm("{ .reg .u64 t; cvta.to.shared.u64 t, %1; cvt.u32.u64 %0, t; }"
        : "=r"(a) : "l"(p));
    return a;
}

__device__ __forceinline__ void ldmx4(uint32_t* r, uint32_t addr) {
    asm volatile("ldmatrix.sync.aligned.m8n8.x4.shared.b16 {%0,%1,%2,%3}, [%4];"
        : "=r"(r[0]), "=r"(r[1]), "=r"(r[2]), "=r"(r[3]) : "r"(addr));
}

__device__ __forceinline__ void mma_bf16(float* c, const uint32_t* a,
                                         uint32_t b0, uint32_t b1) {
    asm volatile(
        "mma.sync.aligned.m16n8k16.row.col.f32.bf16.bf16.f32 "
        "{%0,%1,%2,%3}, {%4,%5,%6,%7}, {%8,%9}, {%0,%1,%2,%3};"
        : "+f"(c[0]), "+f"(c[1]), "+f"(c[2]), "+f"(c[3])
        : "r"(a[0]), "r"(a[1]), "r"(a[2]), "r"(a[3]), "r"(b0), "r"(b1));
}

__device__ __forceinline__ void cp_chunk(uint32_t bufA, uint32_t bufW,
                                         const char* ga, const char* gw,
                                         int tid) {
    #pragma unroll
    for (int j = 0; j < 4; j++) {
        const uint32_t off = (uint32_t)(tid + j * 256) * 16;
        asm volatile("cp.async.cg.shared.global [%0], [%1], 16;"
            :: "r"(bufA + off), "l"(ga + off) : "memory");
        asm volatile("cp.async.cg.shared.global [%0], [%1], 16;"
            :: "r"(bufW + off), "l"(gw + off) : "memory");
    }
    asm volatile("cp.async.commit_group;" ::: "memory");
}

// ---------------------------------------------------------------------------
// split_pack: fp32 [rows x 768] -> bf16 split [rows x 2304] stored as
// pre-swizzled 16KB tile blocks (SW128: 16B group g stored at g ^ (row&7)).
// ---------------------------------------------------------------------------
__device__ __forceinline__ void split_pack_body(
    const float* __restrict__ src, __nv_bfloat16* __restrict__ dst, int lo_seg,
    int u)
{
    const int g   = u % GROUPS_PER_ROW;
    const int m   = u / GROUPS_PER_ROW;
    const int kp0 = g * 8;
    const int seg = kp0 / DD;
    const int kk  = kp0 - seg * DD;
    const float* s = src + (size_t)m * DD + kk;

    __nv_bfloat16 vals[8];
    #pragma unroll
    for (int j = 0; j < 8; j++) {
        float v = s[j];
        __nv_bfloat16 hi = __float2bfloat16(v);
        vals[j] = (seg == lo_seg)
                ? __float2bfloat16(v - __bfloat162float(hi))
                : hi;
    }

    const int mtile = m >> 7, r = m & 127;
    const int kc = kp0 >> 6, c = kp0 & 63;
    const size_t base = ((size_t)mtile * NCHUNK + kc) * (size_t)TILE_BYTES;
    uint32_t off = (uint32_t)(r * 128 + c * 2);
    uint32_t sw  = off ^ ((off >> 3) & 0x70);
    *reinterpret_cast<uint4*>(reinterpret_cast<char*>(dst) + base + sw) =
        *reinterpret_cast<const uint4*>(vals);
}

__global__ __launch_bounds__(256) void split_pack_act(
    const float* __restrict__ src, __nv_bfloat16* __restrict__ dst)
{
    split_pack_body(src, dst, 2, blockIdx.x * 256 + threadIdx.x);
}

// all 4 weights in one launch: blockIdx.y selects matrix
__global__ __launch_bounds__(256) void split_pack_w4(
    const float* __restrict__ w0, const float* __restrict__ w1,
    const float* __restrict__ w2, const float* __restrict__ w3,
    __nv_bfloat16* __restrict__ d0, __nv_bfloat16* __restrict__ d1,
    __nv_bfloat16* __restrict__ d2, __nv_bfloat16* __restrict__ d3)
{
    const float* src; __nv_bfloat16* dst;
    switch (blockIdx.y) {
        case 0:  src = w0; dst = d0; break;
        case 1:  src = w1; dst = d1; break;
        case 2:  src = w2; dst = d2; break;
        default: src = w3; dst = d3; break;
    }
    split_pack_body(src, dst, 1, blockIdx.x * 256 + threadIdx.x);
}

// ---------------------------------------------------------------------------
// GEMM core: CTA 128x128, 8 warps (4Mx2N), K'=2304 in 36 chunks of 64,
// 4-stage cp.async pipeline (depth 3), single __syncthreads per chunk,
// ldmatrix + m16n8k16, fused bias/scale/residual epilogue.
// ---------------------------------------------------------------------------
__device__ __forceinline__ void gemm_core(
    const char* Asrc, const char* Wsrc, const float* __restrict__ bias,
    const float* __restrict__ resid, float* __restrict__ C, float scale,
    int mtile, int ncol, uint32_t sbase)
{
    const int tid  = threadIdx.x;
    const int wid  = tid >> 5, lane = tid & 31;
    const int wm   = wid & 3, wn = wid >> 2;

    float acc[2][8][4];
    #pragma unroll
    for (int mt = 0; mt < 2; mt++)
        #pragma unroll
        for (int nt = 0; nt < 8; nt++)
            #pragma unroll
            for (int j = 0; j < 4; j++) acc[mt][nt][j] = 0.0f;

    // preload stages 0..2
    #pragma unroll
    for (int s = 0; s < NSTAGE - 1; s++) {
        const uint32_t bA = sbase + (uint32_t)s * (2 * TILE_BYTES);
        cp_chunk(bA, bA + TILE_BYTES,
                 Asrc + (size_t)s * TILE_BYTES, Wsrc + (size_t)s * TILE_BYTES,
                 tid);
    }

    for (int i = 0; i < NCHUNK; i++) {
        // complete group i (leave <= in-flight newer groups pending)
        if (i <= NCHUNK - 3)
            asm volatile("cp.async.wait_group 2;" ::: "memory");
        else if (i == NCHUNK - 2)
            asm volatile("cp.async.wait_group 1;" ::: "memory");
        else
            asm volatile("cp.async.wait_group 0;" ::: "memory");
        __syncthreads();

        // refill the stage chunk i-1 just vacated (all warps past it)
        if (i + NSTAGE - 1 < NCHUNK) {
            const int s = (i + NSTAGE - 1) & (NSTAGE - 1);
            const uint32_t bA = sbase + (uint32_t)s * (2 * TILE_BYTES);
            cp_chunk(bA, bA + TILE_BYTES,
                     Asrc + (size_t)(i + NSTAGE - 1) * TILE_BYTES,
                     Wsrc + (size_t)(i + NSTAGE - 1) * TILE_BYTES, tid);
        }

        const uint32_t bufA = sbase + (uint32_t)(i & (NSTAGE - 1)) * (2 * TILE_BYTES);
        const uint32_t bufW = bufA + TILE_BYTES;

        #pragma unroll
        for (int ks = 0; ks < 4; ks++) {
            uint32_t a[2][4];
            #pragma unroll
            for (int mt = 0; mt < 2; mt++) {
                const int r = wm * 32 + mt * 16 + (lane & 15);
                const int gr = ks * 2 + (lane >> 4);
                ldmx4(a[mt], bufA + r * 128 + ((gr ^ (r & 7)) << 4));
            }
            uint32_t b[4][4];
            #pragma unroll
            for (int np = 0; np < 4; np++) {
                const int r = wn * 64 + np * 16 + (lane & 7) + ((lane >> 4) << 3);
                const int gr = ks * 2 + ((lane >> 3) & 1);
                ldmx4(b[np], bufW + r * 128 + ((gr ^ (r & 7)) << 4));
            }
            #pragma unroll
            for (int mt = 0; mt < 2; mt++)
                #pragma unroll
                for (int nt = 0; nt < 8; nt++)
                    mma_bf16(acc[mt][nt], a[mt],
                             b[nt >> 1][(nt & 1) * 2],
                             b[nt >> 1][(nt & 1) * 2 + 1]);
        }
    }

    const int row0 = mtile * MT + wm * 32;
    const int col0 = ncol * NT + wn * 64;
    #pragma unroll
    for (int mt = 0; mt < 2; mt++) {
        #pragma unroll
        for (int nt = 0; nt < 8; nt++) {
            const int r  = row0 + mt * 16 + (lane >> 2);
            const int cc = col0 + nt * 8 + (lane & 3) * 2;
            const float b0 = bias[cc], b1 = bias[cc + 1];
            float2 o0, o1;
            o0.x = (acc[mt][nt][0] + b0) * scale;
            o0.y = (acc[mt][nt][1] + b1) * scale;
            o1.x = (acc[mt][nt][2] + b0) * scale;
            o1.y = (acc[mt][nt][3] + b1) * scale;
            if (resid) {
                o0.x += resid[(size_t)r * DD + cc];
                o0.y += resid[(size_t)r * DD + cc + 1];
                o1.x += resid[(size_t)(r + 8) * DD + cc];
                o1.y += resid[(size_t)(r + 8) * DD + cc + 1];
            }
            *reinterpret_cast<float2*>(C + (size_t)r * DD + cc)       = o0;
            *reinterpret_cast<float2*>(C + (size_t)(r + 8) * DD + cc) = o1;
        }
    }
}

// fused Q/K/V projection: grid (18, 64); blockIdx.x/6 selects the matrix
__global__ __launch_bounds__(256, 1)
void gemm_qkv(const __nv_bfloat16* __restrict__ Ab,
              const __nv_bfloat16* __restrict__ Wq,
              const __nv_bfloat16* __restrict__ Wk,
              const __nv_bfloat16* __restrict__ Wv,
              const float* __restrict__ bq, const float* __restrict__ bk,
              const float* __restrict__ bv,
              float* __restrict__ q, float* __restrict__ k,
              float* __restrict__ v)
{
    extern __shared__ char dyn_smem[];
    const uint32_t sbase = (smem_u32(dyn_smem) + 127u) & ~127u;
    const int sel  = blockIdx.x / 6;
    const int ncol = blockIdx.x % 6;
    const __nv_bfloat16* W = (sel == 0) ? Wq : (sel == 1) ? Wk : Wv;
    const float* bias      = (sel == 0) ? bq : (sel == 1) ? bk : bv;
    float* C               = (sel == 0) ? q  : (sel == 1) ? k  : v;
    const float scale      = (sel == 0) ? 0.125f : 1.0f;

    gemm_core((const char*)Ab + (size_t)blockIdx.y * NCHUNK * TILE_BYTES,
              (const char*)W  + (size_t)ncol * NCHUNK * TILE_BYTES,
              bias, nullptr, C, scale, blockIdx.y, ncol, sbase);
}

// single GEMM (output projection): grid (6, 64)
__global__ __launch_bounds__(256, 1)
void gemm_one(const __nv_bfloat16* __restrict__ Ab,
              const __nv_bfloat16* __restrict__ Wb,
              const float* __restrict__ bias,
              const float* __restrict__ resid,
              float* __restrict__ C, float scale)
{
    extern __shared__ char dyn_smem[];
    const uint32_t sbase = (smem_u32(dyn_smem) + 127u) & ~127u;
    gemm_core((const char*)Ab + (size_t)blockIdx.y * NCHUNK * TILE_BYTES,
              (const char*)Wb + (size_t)blockIdx.x * NCHUNK * TILE_BYTES,
              bias, resid, C, scale, blockIdx.y, blockIdx.x, sbase);
}

// ---------------------------------------------------------------------------
// CSR build
// ---------------------------------------------------------------------------
__global__ void init_cnt() {
    int i = blockIdx.x * blockDim.x + threadIdx.x;
    if (i < NN) g_cnt[i] = 0;
}

__global__ void count_kernel(const int* __restrict__ dst) {
    int e = blockIdx.x * blockDim.x + threadIdx.x;
    if (e < EE) atomicAdd(&g_cnt[dst[e]], 1);
}

__global__ __launch_bounds__(1024) void scan_kernel() {
    __shared__ int ssum[1024];
    const int t = threadIdx.x;
    const int base = t * 8;
    int local[8];
    int s = 0;
    #pragma unroll
    for (int i = 0; i < 8; i++) { local[i] = g_cnt[base + i]; s += local[i]; }
    ssum[t] = s;
    __syncthreads();
    for (int off = 1; off < 1024; off <<= 1) {
        int v = (t >= off) ? ssum[t - off] : 0;
        __syncthreads();
        ssum[t] += v;
        __syncthreads();
    }
    int pre = (t == 0) ? 0 : ssum[t - 1];
    #pragma unroll
    for (int i = 0; i < 8; i++) {
        g_rowptr[base + i] = pre;
        pre += local[i];
        g_cnt[base + i] = 0;
    }
    if (t == 1023) g_rowptr[NN] = pre;
}

__global__ void scatter_kernel(const int* __restrict__ src,
                               const int* __restrict__ dst) {
    int e = blockIdx.x * blockDim.x + threadIdx.x;
    if (e < EE) {
        int d = dst[e];
        int pos = g_rowptr[d] + atomicAdd(&g_cnt[d], 1);
        g_csr_src[pos] = src[e];
    }
}

// ---------------------------------------------------------------------------
// score_csr: block per dst node; q staged in smem once; warps iterate slots
// ---------------------------------------------------------------------------
__global__ __launch_bounds__(256) void score_csr(const float* __restrict__ am) {
    __shared__ float qs[DD];
    const int node = blockIdx.x;
    const int t    = threadIdx.x;
    const int wid  = t >> 5, lane = t & 31;

    qs[t]       = g_q[(size_t)node * DD + t];
    qs[t + 256] = g_q[(size_t)node * DD + t + 256];
    qs[t + 512] = g_q[(size_t)node * DD + t + 512];
    const bool m = (am[node] >= 0.0f);
    __syncthreads();

    const int beg = g_rowptr[node], end = g_rowptr[node + 1];
    for (int slot = beg + wid; slot < end; slot += 8) {
        const float* kr = g_k + (size_t)g_csr_src[slot] * DD;
        float myscore = 0.0f;
        #pragma unroll
        for (int h = 0; h < HH; h++) {
            const int i0 = h * HDIM + lane;
            float p = kr[i0] * qs[i0] + kr[i0 + 32] * qs[i0 + 32];
            #pragma unroll
            for (int off = 16; off; off >>= 1)
                p += __shfl_xor_sync(0xFFFFFFFFu, p, off);
            if (lane == h) myscore = m ? p : -1.0e4f;
        }
        if (lane < HH) g_csr_attn[(size_t)slot * HH + lane] = myscore;
    }
}

// ---------------------------------------------------------------------------
// softmax_csr: one warp per node, lane = head; normalize segment in place
// ---------------------------------------------------------------------------
__global__ __launch_bounds__(256) void softmax_csr() {
    const int node = blockIdx.x * 8 + (threadIdx.x >> 5);
    const int lane = threadIdx.x & 31;
    if (lane >= HH) return;
    const int beg = g_rowptr[node], end = g_rowptr[node + 1];

    float mx = -3.0e38f;
    for (int s = beg; s < end; s++)
        mx = fmaxf(mx, g_csr_attn[(size_t)s * HH + lane]);
    float sum = 0.0f;
    for (int s = beg; s < end; s++) {
        float p = __expf(g_csr_attn[(size_t)s * HH + lane] - mx);
        g_csr_attn[(size_t)s * HH + lane] = p;
        sum += p;
    }
    const float inv = 1.0f / sum;
    for (int s = beg; s < end; s++)
        g_csr_attn[(size_t)s * HH + lane] *= inv;
}

// ---------------------------------------------------------------------------
// agg: hout[n] = 0.9 * sum attn*h[src] + 0.1 * v[n].  192 thr, float4/thread.
// Last step (dst_split != null) writes the bf16 split tiles directly.
// ---------------------------------------------------------------------------
__global__ __launch_bounds__(192) void agg_kernel(
    const float* __restrict__ hin, float* __restrict__ hout,
    __nv_bfloat16* __restrict__ dst_split)
{
    const int node = blockIdx.x;
    const int t    = threadIdx.x;
    const int beg  = g_rowptr[node], end = g_rowptr[node + 1];
    const int head = t >> 4;
    const int col  = t * 4;

    float4 acc = {0.0f, 0.0f, 0.0f, 0.0f};

    __shared__ int   s_src[32];
    __shared__ float s_attn[32 * HH];

    for (int cs = beg; cs < end; cs += 32) {
        const int c = min(32, end - cs);
        __syncthreads();
        if (t < c) s_src[t] = g_csr_src[cs + t];
        for (int i = t; i < c * HH; i += 192)
            s_attn[i] = g_csr_attn[(size_t)cs * HH + i];
        __syncthreads();
        #pragma unroll 4
        for (int j = 0; j < c; j++) {
            const float4 hv = *reinterpret_cast<const float4*>(
                hin + (size_t)s_src[j] * DD + col);
            const float w = s_attn[j * HH + head];
            acc.x += w * hv.x; acc.y += w * hv.y;
            acc.z += w * hv.z; acc.w += w * hv.w;
        }
    }

    const float4 vv = *reinterpret_cast<const float4*>(
        g_v + (size_t)node * DD + col);
    float4 o;
    o.x = 0.9f * acc.x + 0.1f * vv.x;
    o.y = 0.9f * acc.y + 0.1f * vv.y;
    o.z = 0.9f * acc.z + 0.1f * vv.z;
    o.w = 0.9f * acc.w + 0.1f * vv.w;

    if (dst_split) {
        float vals[4] = {o.x, o.y, o.z, o.w};
        __align__(8) __nv_bfloat16 hi[4], lo[4];
        #pragma unroll
        for (int j = 0; j < 4; j++) {
            hi[j] = __float2bfloat16(vals[j]);
            lo[j] = __float2bfloat16(vals[j] - __bfloat162float(hi[j]));
        }
        const int mtile = node >> 7, r = node & 127;
        #pragma unroll
        for (int seg = 0; seg < 3; seg++) {
            const int kp = col + seg * DD;
            const int kc = kp >> 6, cc = kp & 63;
            const size_t base = ((size_t)mtile * NCHUNK + kc) * (size_t)TILE_BYTES;
            uint32_t off = (uint32_t)(r * 128 + cc * 2);
            uint32_t sw  = off ^ ((off >> 3) & 0x70);
            *reinterpret_cast<uint2*>(reinterpret_cast<char*>(dst_split) + base + sw) =
                *reinterpret_cast<const uint2*>(seg == 2 ? lo : hi);
        }
    } else {
        *reinterpret_cast<float4*>(hout + (size_t)node * DD + col) = o;
    }
}

// ---------------------------------------------------------------------------
// LayerNorm: block per row, 256 thr x 3 dims
// ---------------------------------------------------------------------------
__global__ __launch_bounds__(256) void ln_kernel(
    const float* __restrict__ y, const float* __restrict__ gamma,
    const float* __restrict__ beta, float* __restrict__ out)
{
    const int row = blockIdx.x;
    const int t   = threadIdx.x;
    const size_t base = (size_t)row * DD;

    const float x0 = y[base + t];
    const float x1 = y[base + t + 256];
    const float x2 = y[base + t + 512];

    __shared__ float sdata[256];
    sdata[t] = x0 + x1 + x2;
    __syncthreads();
    for (int off = 128; off > 0; off >>= 1) {
        if (t < off) sdata[t] += sdata[t + off];
        __syncthreads();
    }
    const float mu = sdata[0] * (1.0f / DD);
    __syncthreads();

    const float d0 = x0 - mu, d1 = x1 - mu, d2 = x2 - mu;
    sdata[t] = d0 * d0 + d1 * d1 + d2 * d2;
    __syncthreads();
    for (int off = 128; off > 0; off >>= 1) {
        if (t < off) sdata[t] += sdata[t + off];
        __syncthreads();
    }
    const float inv = rsqrtf(sdata[0] * (1.0f / DD) + 1e-12f);

    out[base + t]       = d0 * inv * gamma[t]       + beta[t];
    out[base + t + 256] = d1 * inv * gamma[t + 256] + beta[t + 256];
    out[base + t + 512] = d2 * inv * gamma[t + 512] + beta[t + 512];
}

// ---------------------------------------------------------------------------
// launch
// ---------------------------------------------------------------------------
static float* symF(const void* sym) {
    void* p = nullptr;
    cudaGetSymbolAddress(&p, sym);
    return (float*)p;
}
static __nv_bfloat16* symB(const void* sym) {
    void* p = nullptr;
    cudaGetSymbolAddress(&p, sym);
    return (__nv_bfloat16*)p;
}

extern "C" void kernel_launch(void* const* d_in, const int* in_sizes, int n_in,
                              void* d_out, int out_size) {
    const float* x    = (const float*)d_in[0];
    const float* am   = (const float*)d_in[1];
    const int*   esrc = (const int*)d_in[2];
    const int*   edst = (const int*)d_in[3];
    const float* Wq   = (const float*)d_in[4];
    const float* bq   = (const float*)d_in[5];
    const float* Wk   = (const float*)d_in[6];
    const float* bk   = (const float*)d_in[7];
    const float* Wv   = (const float*)d_in[8];
    const float* bv   = (const float*)d_in[9];
    const float* Wo   = (const float*)d_in[10];
    const float* bo   = (const float*)d_in[11];
    const float* lng  = (const float*)d_in[12];
    const float* lnb  = (const float*)d_in[13];
    float* out = (float*)d_out;

    float* q  = symF(g_q);
    float* k  = symF(g_k);
    float* v  = symF(g_v);
    float* ha = symF(g_ha);
    float* hb = symF(g_hb);
    float* y  = symF(g_y);

    __nv_bfloat16* ax  = symB(g_ax);
    __nv_bfloat16* ah  = symB(g_ah);
    __nv_bfloat16* wqs = symB(g_wqs);
    __nv_bfloat16* wks = symB(g_wks);
    __nv_bfloat16* wvs = symB(g_wvs);
    __nv_bfloat16* wos = symB(g_wos);

    cudaFuncSetAttribute(gemm_qkv, cudaFuncAttributeMaxDynamicSharedMemorySize,
                         GEMM_SMEM);
    cudaFuncSetAttribute(gemm_one, cudaFuncAttributeMaxDynamicSharedMemorySize,
                         GEMM_SMEM);

    const int ACT_BLKS = (NN * GROUPS_PER_ROW) / 256;   // 9216
    const int W_BLKS   = (DD * GROUPS_PER_ROW) / 256;   // 864

    // pack activations and all 4 weights into split-bf16 swizzled tile blocks
    split_pack_act<<<ACT_BLKS, 256>>>(x, ax);
    split_pack_w4<<<dim3(W_BLKS, 4), 256>>>(Wq, Wk, Wv, Wo,
                                            wqs, wks, wvs, wos);

    // fused q/k/v projections, one launch (1152 CTAs)
    gemm_qkv<<<dim3(18, 64), 256, GEMM_SMEM>>>(ax, wqs, wks, wvs,
                                               bq, bk, bv, q, k, v);

    // CSR build
    init_cnt<<<NN / 256, 256>>>();
    count_kernel<<<(EE + 255) / 256, 256>>>(edst);
    scan_kernel<<<1, 1024>>>();
    scatter_kernel<<<(EE + 255) / 256, 256>>>(esrc, edst);

    // fused CSR-order scores + per-node softmax
    score_csr<<<NN, 256>>>(am);
    softmax_csr<<<NN / 8, 256>>>();

    // 5 message-passing steps; last one writes the bf16 split tiles directly
    agg_kernel<<<NN, 192>>>(v,  ha, nullptr);
    agg_kernel<<<NN, 192>>>(ha, hb, nullptr);
    agg_kernel<<<NN, 192>>>(hb, ha, nullptr);
    agg_kernel<<<NN, 192>>>(ha, hb, nullptr);
    agg_kernel<<<NN, 192>>>(hb, nullptr, ah);

    // output projection (+x residual), then LayerNorm
    gemm_one<<<dim3(6, 64), 256, GEMM_SMEM>>>(ah, wos, bo, x, y, 1.0f);
    ln_kernel<<<NN, 256>>>(y, lng, lnb, out);
}

// round 8
// speedup vs baseline: 2.5708x; 1.0433x over previous
#include <cuda_runtime.h>
#include <cuda_bf16.h>
#include <cuda_fp16.h>
#include <cstdint>

// ---------------------------------------------------------------------------
// Problem constants
// ---------------------------------------------------------------------------
#define NN    8192          // B*S nodes
#define DD    768           // hidden dim
#define HH    12            // heads
#define HDIM  64            // head dim
#define EE    131072        // edges

// split-bf16 GEMM constants
#define KSPLIT 2304         // 3*DD (hi|hi|lo vs hi|lo|hi)
#define NCHUNK 36           // KSPLIT/64
#define MT     128          // M tile
#define NT     128          // N tile
#define TILE_BYTES 16384    // 128 rows * 128 bytes
#define GROUPS_PER_ROW (KSPLIT/8)   // 288 16B-units per row
#define NSTAGE 4
#define GEMM_SMEM (NSTAGE * 2 * TILE_BYTES + 128)   // 128KB + pad

// ---------------------------------------------------------------------------
// Scratch (static device globals — no allocation allowed)
// ---------------------------------------------------------------------------
__device__ float g_q[NN * DD];
__device__ float g_v[NN * DD];
__device__ float g_y[NN * DD];

__device__ __half g_kh[NN * DD];         // k (fp16, score gather operand)
__device__ __half g_vh[NN * DD];         // v (fp16, MP step-1 gather operand)
__device__ __half g_hha[NN * DD];        // intermediate h ping
__device__ __half g_hhb[NN * DD];        // intermediate h pong

__device__ int   g_cnt[NN];
__device__ int   g_rowptr[NN + 1];
__device__ int   g_csr_src[EE];          // src node per CSR slot
__device__ float g_csr_attn[EE * HH];    // scores then normalized attn (CSR order)

// split-bf16 operand storage (pre-swizzled 16KB tile blocks)
__device__ __align__(128) __nv_bfloat16 g_ax[(size_t)NN * KSPLIT];   // x  split
__device__ __align__(128) __nv_bfloat16 g_ah[(size_t)NN * KSPLIT];   // h  split
__device__ __align__(128) __nv_bfloat16 g_wqs[(size_t)DD * KSPLIT];
__device__ __align__(128) __nv_bfloat16 g_wks[(size_t)DD * KSPLIT];
__device__ __align__(128) __nv_bfloat16 g_wvs[(size_t)DD * KSPLIT];
__device__ __align__(128) __nv_bfloat16 g_wos[(size_t)DD * KSPLIT];

// ---------------------------------------------------------------------------
// helpers
// ---------------------------------------------------------------------------
__device__ __forceinline__ uint32_t smem_u32(const void* p) {
    uint32_t a;
    asm("{ .reg .u64 t; cvta.to.shared.u64 t, %1; cvt.u32.u64 %0, t; }"
        : "=r"(a) : "l"(p));
    return a;
}

__device__ __forceinline__ void ldmx4(uint32_t* r, uint32_t addr) {
    asm volatile("ldmatrix.sync.aligned.m8n8.x4.shared.b16 {%0,%1,%2,%3}, [%4];"
        : "=r"(r[0]), "=r"(r[1]), "=r"(r[2]), "=r"(r[3]) : "r"(addr));
}

__device__ __forceinline__ void mma_bf16(float* c, const uint32_t* a,
                                         uint32_t b0, uint32_t b1) {
    asm volatile(
        "mma.sync.aligned.m16n8k16.row.col.f32.bf16.bf16.f32 "
        "{%0,%1,%2,%3}, {%4,%5,%6,%7}, {%8,%9}, {%0,%1,%2,%3};"
        : "+f"(c[0]), "+f"(c[1]), "+f"(c[2]), "+f"(c[3])
        : "r"(a[0]), "r"(a[1]), "r"(a[2]), "r"(a[3]), "r"(b0), "r"(b1));
}

__device__ __forceinline__ void cp_chunk(uint32_t bufA, uint32_t bufW,
                                         const char* ga, const char* gw,
                                         int tid) {
    #pragma unroll
    for (int j = 0; j < 4; j++) {
        const uint32_t off = (uint32_t)(tid + j * 256) * 16;
        asm volatile("cp.async.cg.shared.global [%0], [%1], 16;"
            :: "r"(bufA + off), "l"(ga + off) : "memory");
        asm volatile("cp.async.cg.shared.global [%0], [%1], 16;"
            :: "r"(bufW + off), "l"(gw + off) : "memory");
    }
    asm volatile("cp.async.commit_group;" ::: "memory");
}

// ---------------------------------------------------------------------------
// split_pack: fp32 [rows x 768] -> bf16 split [rows x 2304] stored as
// pre-swizzled 16KB tile blocks (SW128: 16B group g stored at g ^ (row&7)).
// ---------------------------------------------------------------------------
__device__ __forceinline__ void split_pack_body(
    const float* __restrict__ src, __nv_bfloat16* __restrict__ dst, int lo_seg,
    int u)
{
    const int g   = u % GROUPS_PER_ROW;
    const int m   = u / GROUPS_PER_ROW;
    const int kp0 = g * 8;
    const int seg = kp0 / DD;
    const int kk  = kp0 - seg * DD;
    const float* s = src + (size_t)m * DD + kk;

    __nv_bfloat16 vals[8];
    #pragma unroll
    for (int j = 0; j < 8; j++) {
        float v = s[j];
        __nv_bfloat16 hi = __float2bfloat16(v);
        vals[j] = (seg == lo_seg)
                ? __float2bfloat16(v - __bfloat162float(hi))
                : hi;
    }

    const int mtile = m >> 7, r = m & 127;
    const int kc = kp0 >> 6, c = kp0 & 63;
    const size_t base = ((size_t)mtile * NCHUNK + kc) * (size_t)TILE_BYTES;
    uint32_t off = (uint32_t)(r * 128 + c * 2);
    uint32_t sw  = off ^ ((off >> 3) & 0x70);
    *reinterpret_cast<uint4*>(reinterpret_cast<char*>(dst) + base + sw) =
        *reinterpret_cast<const uint4*>(vals);
}

__global__ __launch_bounds__(256) void split_pack_act(
    const float* __restrict__ src, __nv_bfloat16* __restrict__ dst)
{
    split_pack_body(src, dst, 2, blockIdx.x * 256 + threadIdx.x);
}

__global__ __launch_bounds__(256) void split_pack_w4(
    const float* __restrict__ w0, const float* __restrict__ w1,
    const float* __restrict__ w2, const float* __restrict__ w3,
    __nv_bfloat16* __restrict__ d0, __nv_bfloat16* __restrict__ d1,
    __nv_bfloat16* __restrict__ d2, __nv_bfloat16* __restrict__ d3)
{
    const float* src; __nv_bfloat16* dst;
    switch (blockIdx.y) {
        case 0:  src = w0; dst = d0; break;
        case 1:  src = w1; dst = d1; break;
        case 2:  src = w2; dst = d2; break;
        default: src = w3; dst = d3; break;
    }
    split_pack_body(src, dst, 1, blockIdx.x * 256 + threadIdx.x);
}

// ---------------------------------------------------------------------------
// GEMM core: CTA 128x128, 8 warps (4Mx2N), K'=2304 in 36 chunks of 64,
// 4-stage cp.async pipeline, ldmatrix + m16n8k16.
// Epilogue writes fp32 C (if non-null) and/or fp16 Ch (if non-null).
// ---------------------------------------------------------------------------
__device__ __forceinline__ void gemm_core(
    const char* Asrc, const char* Wsrc, const float* __restrict__ bias,
    const float* __restrict__ resid, float* __restrict__ C,
    __half* __restrict__ Ch, float scale, int mtile, int ncol, uint32_t sbase)
{
    const int tid  = threadIdx.x;
    const int wid  = tid >> 5, lane = tid & 31;
    const int wm   = wid & 3, wn = wid >> 2;

    float acc[2][8][4];
    #pragma unroll
    for (int mt = 0; mt < 2; mt++)
        #pragma unroll
        for (int nt = 0; nt < 8; nt++)
            #pragma unroll
            for (int j = 0; j < 4; j++) acc[mt][nt][j] = 0.0f;

    #pragma unroll
    for (int s = 0; s < NSTAGE - 1; s++) {
        const uint32_t bA = sbase + (uint32_t)s * (2 * TILE_BYTES);
        cp_chunk(bA, bA + TILE_BYTES,
                 Asrc + (size_t)s * TILE_BYTES, Wsrc + (size_t)s * TILE_BYTES,
                 tid);
    }

    for (int i = 0; i < NCHUNK; i++) {
        if (i <= NCHUNK - 3)
            asm volatile("cp.async.wait_group 2;" ::: "memory");
        else if (i == NCHUNK - 2)
            asm volatile("cp.async.wait_group 1;" ::: "memory");
        else
            asm volatile("cp.async.wait_group 0;" ::: "memory");
        __syncthreads();

        if (i + NSTAGE - 1 < NCHUNK) {
            const int s = (i + NSTAGE - 1) & (NSTAGE - 1);
            const uint32_t bA = sbase + (uint32_t)s * (2 * TILE_BYTES);
            cp_chunk(bA, bA + TILE_BYTES,
                     Asrc + (size_t)(i + NSTAGE - 1) * TILE_BYTES,
                     Wsrc + (size_t)(i + NSTAGE - 1) * TILE_BYTES, tid);
        }

        const uint32_t bufA = sbase + (uint32_t)(i & (NSTAGE - 1)) * (2 * TILE_BYTES);
        const uint32_t bufW = bufA + TILE_BYTES;

        #pragma unroll
        for (int ks = 0; ks < 4; ks++) {
            uint32_t a[2][4];
            #pragma unroll
            for (int mt = 0; mt < 2; mt++) {
                const int r = wm * 32 + mt * 16 + (lane & 15);
                const int gr = ks * 2 + (lane >> 4);
                ldmx4(a[mt], bufA + r * 128 + ((gr ^ (r & 7)) << 4));
            }
            uint32_t b[4][4];
            #pragma unroll
            for (int np = 0; np < 4; np++) {
                const int r = wn * 64 + np * 16 + (lane & 7) + ((lane >> 4) << 3);
                const int gr = ks * 2 + ((lane >> 3) & 1);
                ldmx4(b[np], bufW + r * 128 + ((gr ^ (r & 7)) << 4));
            }
            #pragma unroll
            for (int mt = 0; mt < 2; mt++)
                #pragma unroll
                for (int nt = 0; nt < 8; nt++)
                    mma_bf16(acc[mt][nt], a[mt],
                             b[nt >> 1][(nt & 1) * 2],
                             b[nt >> 1][(nt & 1) * 2 + 1]);
        }
    }

    const int row0 = mtile * MT + wm * 32;
    const int col0 = ncol * NT + wn * 64;
    #pragma unroll
    for (int mt = 0; mt < 2; mt++) {
        #pragma unroll
        for (int nt = 0; nt < 8; nt++) {
            const int r  = row0 + mt * 16 + (lane >> 2);
            const int cc = col0 + nt * 8 + (lane & 3) * 2;
            const float b0 = bias[cc], b1 = bias[cc + 1];
            float2 o0, o1;
            o0.x = (acc[mt][nt][0] + b0) * scale;
            o0.y = (acc[mt][nt][1] + b1) * scale;
            o1.x = (acc[mt][nt][2] + b0) * scale;
            o1.y = (acc[mt][nt][3] + b1) * scale;
            if (resid) {
                o0.x += resid[(size_t)r * DD + cc];
                o0.y += resid[(size_t)r * DD + cc + 1];
                o1.x += resid[(size_t)(r + 8) * DD + cc];
                o1.y += resid[(size_t)(r + 8) * DD + cc + 1];
            }
            if (C) {
                *reinterpret_cast<float2*>(C + (size_t)r * DD + cc)       = o0;
                *reinterpret_cast<float2*>(C + (size_t)(r + 8) * DD + cc) = o1;
            }
            if (Ch) {
                *reinterpret_cast<__half2*>(Ch + (size_t)r * DD + cc) =
                    __floats2half2_rn(o0.x, o0.y);
                *reinterpret_cast<__half2*>(Ch + (size_t)(r + 8) * DD + cc) =
                    __floats2half2_rn(o1.x, o1.y);
            }
        }
    }
}

// fused Q/K/V projection: grid (18, 64); blockIdx.x/6 selects the matrix
// q -> fp32 only; k -> fp16 only; v -> fp32 + fp16
__global__ __launch_bounds__(256, 1)
void gemm_qkv(const __nv_bfloat16* __restrict__ Ab,
              const __nv_bfloat16* __restrict__ Wq,
              const __nv_bfloat16* __restrict__ Wk,
              const __nv_bfloat16* __restrict__ Wv,
              const float* __restrict__ bq, const float* __restrict__ bk,
              const float* __restrict__ bv,
              float* __restrict__ q, __half* __restrict__ kh,
              float* __restrict__ v, __half* __restrict__ vh)
{
    extern __shared__ char dyn_smem[];
    const uint32_t sbase = (smem_u32(dyn_smem) + 127u) & ~127u;
    const int sel  = blockIdx.x / 6;
    const int ncol = blockIdx.x % 6;
    const __nv_bfloat16* W = (sel == 0) ? Wq : (sel == 1) ? Wk : Wv;
    const float* bias      = (sel == 0) ? bq : (sel == 1) ? bk : bv;
    float*  C              = (sel == 0) ? q  : (sel == 1) ? nullptr : v;
    __half* Ch             = (sel == 0) ? nullptr : (sel == 1) ? kh : vh;
    const float scale      = (sel == 0) ? 0.125f : 1.0f;

    gemm_core((const char*)Ab + (size_t)blockIdx.y * NCHUNK * TILE_BYTES,
              (const char*)W  + (size_t)ncol * NCHUNK * TILE_BYTES,
              bias, nullptr, C, Ch, scale, blockIdx.y, ncol, sbase);
}

// single GEMM (output projection): grid (6, 64)
__global__ __launch_bounds__(256, 1)
void gemm_one(const __nv_bfloat16* __restrict__ Ab,
              const __nv_bfloat16* __restrict__ Wb,
              const float* __restrict__ bias,
              const float* __restrict__ resid,
              float* __restrict__ C, float scale)
{
    extern __shared__ char dyn_smem[];
    const uint32_t sbase = (smem_u32(dyn_smem) + 127u) & ~127u;
    gemm_core((const char*)Ab + (size_t)blockIdx.y * NCHUNK * TILE_BYTES,
              (const char*)Wb + (size_t)blockIdx.x * NCHUNK * TILE_BYTES,
              bias, resid, C, nullptr, scale, blockIdx.y, blockIdx.x, sbase);
}

// ---------------------------------------------------------------------------
// CSR build
// ---------------------------------------------------------------------------
__global__ void init_cnt() {
    int i = blockIdx.x * blockDim.x + threadIdx.x;
    if (i < NN) g_cnt[i] = 0;
}

__global__ void count_kernel(const int* __restrict__ dst) {
    int e = blockIdx.x * blockDim.x + threadIdx.x;
    if (e < EE) atomicAdd(&g_cnt[dst[e]], 1);
}

__global__ __launch_bounds__(1024) void scan_kernel() {
    __shared__ int ssum[1024];
    const int t = threadIdx.x;
    const int base = t * 8;
    int local[8];
    int s = 0;
    #pragma unroll
    for (int i = 0; i < 8; i++) { local[i] = g_cnt[base + i]; s += local[i]; }
    ssum[t] = s;
    __syncthreads();
    for (int off = 1; off < 1024; off <<= 1) {
        int v = (t >= off) ? ssum[t - off] : 0;
        __syncthreads();
        ssum[t] += v;
        __syncthreads();
    }
    int pre = (t == 0) ? 0 : ssum[t - 1];
    #pragma unroll
    for (int i = 0; i < 8; i++) {
        g_rowptr[base + i] = pre;
        pre += local[i];
        g_cnt[base + i] = 0;
    }
    if (t == 1023) g_rowptr[NN] = pre;
}

__global__ void scatter_kernel(const int* __restrict__ src,
                               const int* __restrict__ dst) {
    int e = blockIdx.x * blockDim.x + threadIdx.x;
    if (e < EE) {
        int d = dst[e];
        int pos = g_rowptr[d] + atomicAdd(&g_cnt[d], 1);
        g_csr_src[pos] = src[e];
    }
}

// ---------------------------------------------------------------------------
// score_csr: block per dst node; q (fp32) staged in smem; k gathered as fp16.
// lane covers head elements {2*lane, 2*lane+1} via one half2 load.
// ---------------------------------------------------------------------------
__global__ __launch_bounds__(256) void score_csr(const float* __restrict__ am) {
    __shared__ float qs[DD];
    const int node = blockIdx.x;
    const int t    = threadIdx.x;
    const int wid  = t >> 5, lane = t & 31;

    qs[t]       = g_q[(size_t)node * DD + t];
    qs[t + 256] = g_q[(size_t)node * DD + t + 256];
    qs[t + 512] = g_q[(size_t)node * DD + t + 512];
    const bool m = (am[node] >= 0.0f);
    __syncthreads();

    const int beg = g_rowptr[node], end = g_rowptr[node + 1];
    for (int slot = beg + wid; slot < end; slot += 8) {
        const __half* kr = g_kh + (size_t)g_csr_src[slot] * DD;
        float myscore = 0.0f;
        #pragma unroll
        for (int h = 0; h < HH; h++) {
            const int i0 = h * HDIM + lane * 2;
            const float2 kf = __half22float2(
                *reinterpret_cast<const __half2*>(kr + i0));
            const float2 qf = *reinterpret_cast<const float2*>(qs + i0);
            float p = kf.x * qf.x + kf.y * qf.y;
            #pragma unroll
            for (int off = 16; off; off >>= 1)
                p += __shfl_xor_sync(0xFFFFFFFFu, p, off);
            if (lane == h) myscore = m ? p : -1.0e4f;
        }
        if (lane < HH) g_csr_attn[(size_t)slot * HH + lane] = myscore;
    }
}

// ---------------------------------------------------------------------------
// softmax_csr: one warp per node, lane = head; normalize segment in place
// ---------------------------------------------------------------------------
__global__ __launch_bounds__(256) void softmax_csr() {
    const int node = blockIdx.x * 8 + (threadIdx.x >> 5);
    const int lane = threadIdx.x & 31;
    if (lane >= HH) return;
    const int beg = g_rowptr[node], end = g_rowptr[node + 1];

    float mx = -3.0e38f;
    for (int s = beg; s < end; s++)
        mx = fmaxf(mx, g_csr_attn[(size_t)s * HH + lane]);
    float sum = 0.0f;
    for (int s = beg; s < end; s++) {
        float p = __expf(g_csr_attn[(size_t)s * HH + lane] - mx);
        g_csr_attn[(size_t)s * HH + lane] = p;
        sum += p;
    }
    const float inv = 1.0f / sum;
    for (int s = beg; s < end; s++)
        g_csr_attn[(size_t)s * HH + lane] *= inv;
}

// ---------------------------------------------------------------------------
// agg: hout[n] = 0.9 * sum attn*h[src] + 0.1 * v[n].  192 thr, 4 elems/thread.
// h gathered/stored as fp16; accumulation + v blend in fp32.
// Last step (dst_split != null) writes bf16 split tiles from fp32 accumulator.
// ---------------------------------------------------------------------------
__global__ __launch_bounds__(192) void agg_kernel(
    const __half* __restrict__ hin, __half* __restrict__ hout,
    __nv_bfloat16* __restrict__ dst_split)
{
    const int node = blockIdx.x;
    const int t    = threadIdx.x;
    const int beg  = g_rowptr[node], end = g_rowptr[node + 1];
    const int head = t >> 4;
    const int col  = t * 4;

    float4 acc = {0.0f, 0.0f, 0.0f, 0.0f};

    __shared__ int   s_src[32];
    __shared__ float s_attn[32 * HH];

    for (int cs = beg; cs < end; cs += 32) {
        const int c = min(32, end - cs);
        __syncthreads();
        if (t < c) s_src[t] = g_csr_src[cs + t];
        for (int i = t; i < c * HH; i += 192)
            s_attn[i] = g_csr_attn[(size_t)cs * HH + i];
        __syncthreads();
        #pragma unroll 4
        for (int j = 0; j < c; j++) {
            const __half2* hp = reinterpret_cast<const __half2*>(
                hin + (size_t)s_src[j] * DD + col);
            const float2 h0 = __half22float2(hp[0]);
            const float2 h1 = __half22float2(hp[1]);
            const float w = s_attn[j * HH + head];
            acc.x += w * h0.x; acc.y += w * h0.y;
            acc.z += w * h1.x; acc.w += w * h1.y;
        }
    }

    const float4 vv = *reinterpret_cast<const float4*>(
        g_v + (size_t)node * DD + col);
    float4 o;
    o.x = 0.9f * acc.x + 0.1f * vv.x;
    o.y = 0.9f * acc.y + 0.1f * vv.y;
    o.z = 0.9f * acc.z + 0.1f * vv.z;
    o.w = 0.9f * acc.w + 0.1f * vv.w;

    if (dst_split) {
        float vals[4] = {o.x, o.y, o.z, o.w};
        __align__(8) __nv_bfloat16 hi[4], lo[4];
        #pragma unroll
        for (int j = 0; j < 4; j++) {
            hi[j] = __float2bfloat16(vals[j]);
            lo[j] = __float2bfloat16(vals[j] - __bfloat162float(hi[j]));
        }
        const int mtile = node >> 7, r = node & 127;
        #pragma unroll
        for (int seg = 0; seg < 3; seg++) {
            const int kp = col + seg * DD;
            const int kc = kp >> 6, cc = kp & 63;
            const size_t base = ((size_t)mtile * NCHUNK + kc) * (size_t)TILE_BYTES;
            uint32_t off = (uint32_t)(r * 128 + cc * 2);
            uint32_t sw  = off ^ ((off >> 3) & 0x70);
            *reinterpret_cast<uint2*>(reinterpret_cast<char*>(dst_split) + base + sw) =
                *reinterpret_cast<const uint2*>(seg == 2 ? lo : hi);
        }
    } else {
        __half2* op = reinterpret_cast<__half2*>(hout + (size_t)node * DD + col);
        op[0] = __floats2half2_rn(o.x, o.y);
        op[1] = __floats2half2_rn(o.z, o.w);
    }
}

// ---------------------------------------------------------------------------
// LayerNorm: block per row, 256 thr x 3 dims
// ---------------------------------------------------------------------------
__global__ __launch_bounds__(256) void ln_kernel(
    const float* __restrict__ y, const float* __restrict__ gamma,
    const float* __restrict__ beta, float* __restrict__ out)
{
    const int row = blockIdx.x;
    const int t   = threadIdx.x;
    const size_t base = (size_t)row * DD;

    const float x0 = y[base + t];
    const float x1 = y[base + t + 256];
    const float x2 = y[base + t + 512];

    __shared__ float sdata[256];
    sdata[t] = x0 + x1 + x2;
    __syncthreads();
    for (int off = 128; off > 0; off >>= 1) {
        if (t < off) sdata[t] += sdata[t + off];
        __syncthreads();
    }
    const float mu = sdata[0] * (1.0f / DD);
    __syncthreads();

    const float d0 = x0 - mu, d1 = x1 - mu, d2 = x2 - mu;
    sdata[t] = d0 * d0 + d1 * d1 + d2 * d2;
    __syncthreads();
    for (int off = 128; off > 0; off >>= 1) {
        if (t < off) sdata[t] += sdata[t + off];
        __syncthreads();
    }
    const float inv = rsqrtf(sdata[0] * (1.0f / DD) + 1e-12f);

    out[base + t]       = d0 * inv * gamma[t]       + beta[t];
    out[base + t + 256] = d1 * inv * gamma[t + 256] + beta[t + 256];
    out[base + t + 512] = d2 * inv * gamma[t + 512] + beta[t + 512];
}

// ---------------------------------------------------------------------------
// launch
// ---------------------------------------------------------------------------
static float* symF(const void* sym) {
    void* p = nullptr;
    cudaGetSymbolAddress(&p, sym);
    return (float*)p;
}
static __nv_bfloat16* symB(const void* sym) {
    void* p = nullptr;
    cudaGetSymbolAddress(&p, sym);
    return (__nv_bfloat16*)p;
}
static __half* symH(const void* sym) {
    void* p = nullptr;
    cudaGetSymbolAddress(&p, sym);
    return (__half*)p;
}

extern "C" void kernel_launch(void* const* d_in, const int* in_sizes, int n_in,
                              void* d_out, int out_size) {
    const float* x    = (const float*)d_in[0];
    const float* am   = (const float*)d_in[1];
    const int*   esrc = (const int*)d_in[2];
    const int*   edst = (const int*)d_in[3];
    const float* Wq   = (const float*)d_in[4];
    const float* bq   = (const float*)d_in[5];
    const float* Wk   = (const float*)d_in[6];
    const float* bk   = (const float*)d_in[7];
    const float* Wv   = (const float*)d_in[8];
    const float* bv   = (const float*)d_in[9];
    const float* Wo   = (const float*)d_in[10];
    const float* bo   = (const float*)d_in[11];
    const float* lng  = (const float*)d_in[12];
    const float* lnb  = (const float*)d_in[13];
    float* out = (float*)d_out;

    float* q  = symF(g_q);
    float* v  = symF(g_v);
    float* y  = symF(g_y);

    __half* kh  = symH(g_kh);
    __half* vh  = symH(g_vh);
    __half* hha = symH(g_hha);
    __half* hhb = symH(g_hhb);

    __nv_bfloat16* ax  = symB(g_ax);
    __nv_bfloat16* ah  = symB(g_ah);
    __nv_bfloat16* wqs = symB(g_wqs);
    __nv_bfloat16* wks = symB(g_wks);
    __nv_bfloat16* wvs = symB(g_wvs);
    __nv_bfloat16* wos = symB(g_wos);

    cudaFuncSetAttribute(gemm_qkv, cudaFuncAttributeMaxDynamicSharedMemorySize,
                         GEMM_SMEM);
    cudaFuncSetAttribute(gemm_one, cudaFuncAttributeMaxDynamicSharedMemorySize,
                         GEMM_SMEM);

    const int ACT_BLKS = (NN * GROUPS_PER_ROW) / 256;   // 9216
    const int W_BLKS   = (DD * GROUPS_PER_ROW) / 256;   // 864

    // pack activations and all 4 weights into split-bf16 swizzled tile blocks
    split_pack_act<<<ACT_BLKS, 256>>>(x, ax);
    split_pack_w4<<<dim3(W_BLKS, 4), 256>>>(Wq, Wk, Wv, Wo,
                                            wqs, wks, wvs, wos);

    // fused q/k/v projections (k -> fp16 only, v -> fp32 + fp16)
    gemm_qkv<<<dim3(18, 64), 256, GEMM_SMEM>>>(ax, wqs, wks, wvs,
                                               bq, bk, bv, q, kh, v, vh);

    // CSR build
    init_cnt<<<NN / 256, 256>>>();
    count_kernel<<<(EE + 255) / 256, 256>>>(edst);
    scan_kernel<<<1, 1024>>>();
    scatter_kernel<<<(EE + 255) / 256, 256>>>(esrc, edst);

    // fused CSR-order scores + per-node softmax
    score_csr<<<NN, 256>>>(am);
    softmax_csr<<<NN / 8, 256>>>();

    // 5 message-passing steps on fp16 h; last writes bf16 split tiles
    agg_kernel<<<NN, 192>>>(vh,  hha, nullptr);
    agg_kernel<<<NN, 192>>>(hha, hhb, nullptr);
    agg_kernel<<<NN, 192>>>(hhb, hha, nullptr);
    agg_kernel<<<NN, 192>>>(hha, hhb, nullptr);
    agg_kernel<<<NN, 192>>>(hhb, nullptr, ah);

    // output projection (+x residual), then LayerNorm
    gemm_one<<<dim3(6, 64), 256, GEMM_SMEM>>>(ah, wos, bo, x, y, 1.0f);
    ln_kernel<<<NN, 256>>>(y, lng, lnb, out);
}

// round 11
// speedup vs baseline: 2.6128x; 1.0163x over previous
#include <cuda_runtime.h>
#include <cuda_bf16.h>
#include <cuda_fp16.h>
#include <cstdint>

// ---------------------------------------------------------------------------
// Problem constants
// ---------------------------------------------------------------------------
#define NN    8192          // B*S nodes
#define DD    768           // hidden dim
#define HH    12            // heads
#define HDIM  64            // head dim
#define EE    131072        // edges
#define DEGCAP 128          // smem softmax capacity (max degree ~40 expected)

// split-bf16 GEMM constants
#define KSPLIT 2304         // 3*DD (hi|hi|lo vs hi|lo|hi)
#define NCHUNK 36           // KSPLIT/64
#define MT     128          // M tile
#define NT     128          // N tile
#define TILE_BYTES 16384    // 128 rows * 128 bytes
#define GROUPS_PER_ROW (KSPLIT/8)   // 288 16B-units per row
#define NSTAGE 4
#define GEMM_SMEM (NSTAGE * 2 * TILE_BYTES + 128)   // 128KB + pad

// ---------------------------------------------------------------------------
// Scratch (static device globals — no allocation allowed)
// ---------------------------------------------------------------------------
__device__ float g_q[NN * DD];
__device__ float g_y[NN * DD];

__device__ __half g_kh[NN * DD];         // k (fp16, score gather operand)
__device__ __half g_vh[NN * DD];         // v (fp16, gather + blend operand)
__device__ __half g_hha[NN * DD];        // intermediate h ping
__device__ __half g_hhb[NN * DD];        // intermediate h pong

__device__ int   g_cnt[NN];              // starts 0 (BSS); reset by score kernel
__device__ int   g_rowptr[NN + 1];
__device__ int   g_csr_src[EE];          // src node per CSR slot
__device__ float g_csr_attn[EE * HH];    // normalized attn (CSR order)

// split-bf16 operand storage (pre-swizzled 16KB tile blocks)
__device__ __align__(128) __nv_bfloat16 g_ax[(size_t)NN * KSPLIT];   // x  split
__device__ __align__(128) __nv_bfloat16 g_ah[(size_t)NN * KSPLIT];   // h  split
__device__ __align__(128) __nv_bfloat16 g_wqs[(size_t)DD * KSPLIT];
__device__ __align__(128) __nv_bfloat16 g_wks[(size_t)DD * KSPLIT];
__device__ __align__(128) __nv_bfloat16 g_wvs[(size_t)DD * KSPLIT];
__device__ __align__(128) __nv_bfloat16 g_wos[(size_t)DD * KSPLIT];

// ---------------------------------------------------------------------------
// helpers
// ---------------------------------------------------------------------------
__device__ __forceinline__ uint32_t smem_u32(const void* p) {
    uint32_t a;
    asm("{ .reg .u64 t; cvta.to.shared.u64 t, %1; cvt.u32.u64 %0, t; }"
        : "=r"(a) : "l"(p));
    return a;
}

__device__ __forceinline__ void ldmx4(uint32_t* r, uint32_t addr) {
    asm volatile("ldmatrix.sync.aligned.m8n8.x4.shared.b16 {%0,%1,%2,%3}, [%4];"
        : "=r"(r[0]), "=r"(r[1]), "=r"(r[2]), "=r"(r[3]) : "r"(addr));
}

__device__ __forceinline__ void mma_bf16(float* c, const uint32_t* a,
                                         uint32_t b0, uint32_t b1) {
    asm volatile(
        "mma.sync.aligned.m16n8k16.row.col.f32.bf16.bf16.f32 "
        "{%0,%1,%2,%3}, {%4,%5,%6,%7}, {%8,%9}, {%0,%1,%2,%3};"
        : "+f"(c[0]), "+f"(c[1]), "+f"(c[2]), "+f"(c[3])
        : "r"(a[0]), "r"(a[1]), "r"(a[2]), "r"(a[3]), "r"(b0), "r"(b1));
}

__device__ __forceinline__ void cp_chunk(uint32_t bufA, uint32_t bufW,
                                         const char* ga, const char* gw,
                                         int tid) {
    #pragma unroll
    for (int j = 0; j < 4; j++) {
        const uint32_t off = (uint32_t)(tid + j * 256) * 16;
        asm volatile("cp.async.cg.shared.global [%0], [%1], 16;"
            :: "r"(bufA + off), "l"(ga + off) : "memory");
        asm volatile("cp.async.cg.shared.global [%0], [%1], 16;"
            :: "r"(bufW + off), "l"(gw + off) : "memory");
    }
    asm volatile("cp.async.commit_group;" ::: "memory");
}

// ---------------------------------------------------------------------------
// split_pack: fp32 [rows x 768] -> bf16 split [rows x 2304] stored as
// pre-swizzled 16KB tile blocks (SW128: 16B group g stored at g ^ (row&7)).
// ---------------------------------------------------------------------------
__device__ __forceinline__ void split_pack_body(
    const float* __restrict__ src, __nv_bfloat16* __restrict__ dst, int lo_seg,
    int u)
{
    const int g   = u % GROUPS_PER_ROW;
    const int m   = u / GROUPS_PER_ROW;
    const int kp0 = g * 8;
    const int seg = kp0 / DD;
    const int kk  = kp0 - seg * DD;
    const float* s = src + (size_t)m * DD + kk;

    __nv_bfloat16 vals[8];
    #pragma unroll
    for (int j = 0; j < 8; j++) {
        float v = s[j];
        __nv_bfloat16 hi = __float2bfloat16(v);
        vals[j] = (seg == lo_seg)
                ? __float2bfloat16(v - __bfloat162float(hi))
                : hi;
    }

    const int mtile = m >> 7, r = m & 127;
    const int kc = kp0 >> 6, c = kp0 & 63;
    const size_t base = ((size_t)mtile * NCHUNK + kc) * (size_t)TILE_BYTES;
    uint32_t off = (uint32_t)(r * 128 + c * 2);
    uint32_t sw  = off ^ ((off >> 3) & 0x70);
    *reinterpret_cast<uint4*>(reinterpret_cast<char*>(dst) + base + sw) =
        *reinterpret_cast<const uint4*>(vals);
}

__global__ __launch_bounds__(256) void split_pack_act(
    const float* __restrict__ src, __nv_bfloat16* __restrict__ dst)
{
    split_pack_body(src, dst, 2, blockIdx.x * 256 + threadIdx.x);
}

__global__ __launch_bounds__(256) void split_pack_w4(
    const float* __restrict__ w0, const float* __restrict__ w1,
    const float* __restrict__ w2, const float* __restrict__ w3,
    __nv_bfloat16* __restrict__ d0, __nv_bfloat16* __restrict__ d1,
    __nv_bfloat16* __restrict__ d2, __nv_bfloat16* __restrict__ d3)
{
    const float* src; __nv_bfloat16* dst;
    switch (blockIdx.y) {
        case 0:  src = w0; dst = d0; break;
        case 1:  src = w1; dst = d1; break;
        case 2:  src = w2; dst = d2; break;
        default: src = w3; dst = d3; break;
    }
    split_pack_body(src, dst, 1, blockIdx.x * 256 + threadIdx.x);
}

// ---------------------------------------------------------------------------
// GEMM core: CTA 128x128, 8 warps (4Mx2N), K'=2304 in 36 chunks of 64,
// 4-stage cp.async pipeline, ldmatrix + m16n8k16.
// Epilogue writes fp32 C (if non-null) and/or fp16 Ch (if non-null).
// ---------------------------------------------------------------------------
__device__ __forceinline__ void gemm_core(
    const char* Asrc, const char* Wsrc, const float* __restrict__ bias,
    const float* __restrict__ resid, float* __restrict__ C,
    __half* __restrict__ Ch, float scale, int mtile, int ncol, uint32_t sbase)
{
    const int tid  = threadIdx.x;
    const int wid  = tid >> 5, lane = tid & 31;
    const int wm   = wid & 3, wn = wid >> 2;

    float acc[2][8][4];
    #pragma unroll
    for (int mt = 0; mt < 2; mt++)
        #pragma unroll
        for (int nt = 0; nt < 8; nt++)
            #pragma unroll
            for (int j = 0; j < 4; j++) acc[mt][nt][j] = 0.0f;

    #pragma unroll
    for (int s = 0; s < NSTAGE - 1; s++) {
        const uint32_t bA = sbase + (uint32_t)s * (2 * TILE_BYTES);
        cp_chunk(bA, bA + TILE_BYTES,
                 Asrc + (size_t)s * TILE_BYTES, Wsrc + (size_t)s * TILE_BYTES,
                 tid);
    }

    for (int i = 0; i < NCHUNK; i++) {
        if (i <= NCHUNK - 3)
            asm volatile("cp.async.wait_group 2;" ::: "memory");
        else if (i == NCHUNK - 2)
            asm volatile("cp.async.wait_group 1;" ::: "memory");
        else
            asm volatile("cp.async.wait_group 0;" ::: "memory");
        __syncthreads();

        if (i + NSTAGE - 1 < NCHUNK) {
            const int s = (i + NSTAGE - 1) & (NSTAGE - 1);
            const uint32_t bA = sbase + (uint32_t)s * (2 * TILE_BYTES);
            cp_chunk(bA, bA + TILE_BYTES,
                     Asrc + (size_t)(i + NSTAGE - 1) * TILE_BYTES,
                     Wsrc + (size_t)(i + NSTAGE - 1) * TILE_BYTES, tid);
        }

        const uint32_t bufA = sbase + (uint32_t)(i & (NSTAGE - 1)) * (2 * TILE_BYTES);
        const uint32_t bufW = bufA + TILE_BYTES;

        #pragma unroll
        for (int ks = 0; ks < 4; ks++) {
            uint32_t a[2][4];
            #pragma unroll
            for (int mt = 0; mt < 2; mt++) {
                const int r = wm * 32 + mt * 16 + (lane & 15);
                const int gr = ks * 2 + (lane >> 4);
                ldmx4(a[mt], bufA + r * 128 + ((gr ^ (r & 7)) << 4));
            }
            uint32_t b[4][4];
            #pragma unroll
            for (int np = 0; np < 4; np++) {
                const int r = wn * 64 + np * 16 + (lane & 7) + ((lane >> 4) << 3);
                const int gr = ks * 2 + ((lane >> 3) & 1);
                ldmx4(b[np], bufW + r * 128 + ((gr ^ (r & 7)) << 4));
            }
            #pragma unroll
            for (int mt = 0; mt < 2; mt++)
                #pragma unroll
                for (int nt = 0; nt < 8; nt++)
                    mma_bf16(acc[mt][nt], a[mt],
                             b[nt >> 1][(nt & 1) * 2],
                             b[nt >> 1][(nt & 1) * 2 + 1]);
        }
    }

    const int row0 = mtile * MT + wm * 32;
    const int col0 = ncol * NT + wn * 64;
    #pragma unroll
    for (int mt = 0; mt < 2; mt++) {
        #pragma unroll
        for (int nt = 0; nt < 8; nt++) {
            const int r  = row0 + mt * 16 + (lane >> 2);
            const int cc = col0 + nt * 8 + (lane & 3) * 2;
            const float b0 = bias[cc], b1 = bias[cc + 1];
            float2 o0, o1;
            o0.x = (acc[mt][nt][0] + b0) * scale;
            o0.y = (acc[mt][nt][1] + b1) * scale;
            o1.x = (acc[mt][nt][2] + b0) * scale;
            o1.y = (acc[mt][nt][3] + b1) * scale;
            if (resid) {
                o0.x += resid[(size_t)r * DD + cc];
                o0.y += resid[(size_t)r * DD + cc + 1];
                o1.x += resid[(size_t)(r + 8) * DD + cc];
                o1.y += resid[(size_t)(r + 8) * DD + cc + 1];
            }
            if (C) {
                *reinterpret_cast<float2*>(C + (size_t)r * DD + cc)       = o0;
                *reinterpret_cast<float2*>(C + (size_t)(r + 8) * DD + cc) = o1;
            }
            if (Ch) {
                *reinterpret_cast<__half2*>(Ch + (size_t)r * DD + cc) =
                    __floats2half2_rn(o0.x, o0.y);
                *reinterpret_cast<__half2*>(Ch + (size_t)(r + 8) * DD + cc) =
                    __floats2half2_rn(o1.x, o1.y);
            }
        }
    }
}

// fused Q/K/V projection: grid (18, 64); blockIdx.x/6 selects the matrix
// q -> fp32 only; k -> fp16 only; v -> fp16 only
__global__ __launch_bounds__(256, 1)
void gemm_qkv(const __nv_bfloat16* __restrict__ Ab,
              const __nv_bfloat16* __restrict__ Wq,
              const __nv_bfloat16* __restrict__ Wk,
              const __nv_bfloat16* __restrict__ Wv,
              const float* __restrict__ bq, const float* __restrict__ bk,
              const float* __restrict__ bv,
              float* __restrict__ q, __half* __restrict__ kh,
              __half* __restrict__ vh)
{
    extern __shared__ char dyn_smem[];
    const uint32_t sbase = (smem_u32(dyn_smem) + 127u) & ~127u;
    const int sel  = blockIdx.x / 6;
    const int ncol = blockIdx.x % 6;
    const __nv_bfloat16* W = (sel == 0) ? Wq : (sel == 1) ? Wk : Wv;
    const float* bias      = (sel == 0) ? bq : (sel == 1) ? bk : bv;
    float*  C              = (sel == 0) ? q  : nullptr;
    __half* Ch             = (sel == 0) ? nullptr : (sel == 1) ? kh : vh;
    const float scale      = (sel == 0) ? 0.125f : 1.0f;

    gemm_core((const char*)Ab + (size_t)blockIdx.y * NCHUNK * TILE_BYTES,
              (const char*)W  + (size_t)ncol * NCHUNK * TILE_BYTES,
              bias, nullptr, C, Ch, scale, blockIdx.y, ncol, sbase);
}

// single GEMM (output projection): grid (6, 64)
__global__ __launch_bounds__(256, 1)
void gemm_one(const __nv_bfloat16* __restrict__ Ab,
              const __nv_bfloat16* __restrict__ Wb,
              const float* __restrict__ bias,
              const float* __restrict__ resid,
              float* __restrict__ C, float scale)
{
    extern __shared__ char dyn_smem[];
    const uint32_t sbase = (smem_u32(dyn_smem) + 127u) & ~127u;
    gemm_core((const char*)Ab + (size_t)blockIdx.y * NCHUNK * TILE_BYTES,
              (const char*)Wb + (size_t)blockIdx.x * NCHUNK * TILE_BYTES,
              bias, resid, C, nullptr, scale, blockIdx.y, blockIdx.x, sbase);
}

// ---------------------------------------------------------------------------
// CSR build (g_cnt == 0 at call entry: zero-init BSS on first call, reset by
// score_softmax at end of every call)
// ---------------------------------------------------------------------------
__global__ void count_kernel(const int* __restrict__ dst) {
    int e = blockIdx.x * blockDim.x + threadIdx.x;
    if (e < EE) atomicAdd(&g_cnt[dst[e]], 1);
}

__global__ __launch_bounds__(1024) void scan_kernel() {
    __shared__ int ssum[1024];
    const int t = threadIdx.x;
    const int base = t * 8;
    int local[8];
    int s = 0;
    #pragma unroll
    for (int i = 0; i < 8; i++) { local[i] = g_cnt[base + i]; s += local[i]; }
    ssum[t] = s;
    __syncthreads();
    for (int off = 1; off < 1024; off <<= 1) {
        int v = (t >= off) ? ssum[t - off] : 0;
        __syncthreads();
        ssum[t] += v;
        __syncthreads();
    }
    int pre = (t == 0) ? 0 : ssum[t - 1];
    #pragma unroll
    for (int i = 0; i < 8; i++) {
        g_rowptr[base + i] = pre;
        pre += local[i];
        g_cnt[base + i] = 0;               // reset for scatter pass
    }
    if (t == 1023) g_rowptr[NN] = pre;
}

__global__ void scatter_kernel(const int* __restrict__ src,
                               const int* __restrict__ dst) {
    int e = blockIdx.x * blockDim.x + threadIdx.x;
    if (e < EE) {
        int d = dst[e];
        int pos = g_rowptr[d] + atomicAdd(&g_cnt[d], 1);
        g_csr_src[pos] = src[e];
    }
}

// ---------------------------------------------------------------------------
// score_softmax: block per dst node. q (fp32) staged in smem; k gathered fp16;
// raw scores staged in smem; parallel per-head softmax; normalized attn
// written once to g_csr_attn. Global fallback for deg > DEGCAP.
// Also resets g_cnt[node] = 0 for the next call's count.
// ---------------------------------------------------------------------------
__global__ __launch_bounds__(256) void score_softmax(const float* __restrict__ am) {
    __shared__ float qs[DD];
    __shared__ float sc[DEGCAP * HH];
    __shared__ float red[8 * HH];
    __shared__ float mxs[HH], invs[HH];

    const int node = blockIdx.x;
    const int t    = threadIdx.x;
    const int wid  = t >> 5, lane = t & 31;

    qs[t]       = g_q[(size_t)node * DD + t];
    qs[t + 256] = g_q[(size_t)node * DD + t + 256];
    qs[t + 512] = g_q[(size_t)node * DD + t + 512];
    const bool m = (am[node] >= 0.0f);
    __syncthreads();

    const int beg = g_rowptr[node];
    const int deg = g_rowptr[node + 1] - beg;

    for (int s = wid; s < deg; s += 8) {
        const __half* kr = g_kh + (size_t)g_csr_src[beg + s] * DD;
        float myscore = 0.0f;
        #pragma unroll
        for (int h = 0; h < HH; h++) {
            const int i0 = h * HDIM + lane * 2;
            const float2 kf = __half22float2(
                *reinterpret_cast<const __half2*>(kr + i0));
            const float2 qf = *reinterpret_cast<const float2*>(qs + i0);
            float p = kf.x * qf.x + kf.y * qf.y;
            #pragma unroll
            for (int off = 16; off; off >>= 1)
                p += __shfl_xor_sync(0xFFFFFFFFu, p, off);
            if (lane == h) myscore = m ? p : -1.0e4f;
        }
        if (lane < HH) {
            if (s < DEGCAP) sc[s * HH + lane] = myscore;
            else g_csr_attn[(size_t)(beg + s) * HH + lane] = myscore;
        }
    }
    __syncthreads();

    if (deg <= DEGCAP) {
        // parallel softmax over smem scores
        if (t < 8 * HH) {
            const int h = t % HH, g = t / HH;
            float mx = -3.0e38f;
            for (int s = g; s < deg; s += 8) mx = fmaxf(mx, sc[s * HH + h]);
            red[g * HH + h] = mx;
        }
        __syncthreads();
        if (t < HH) {
            float mx = red[t];
            #pragma unroll
            for (int g = 1; g < 8; g++) mx = fmaxf(mx, red[g * HH + t]);
            mxs[t] = mx;
        }
        __syncthreads();
        if (t < 8 * HH) {
            const int h = t % HH, g = t / HH;
            const float mx = mxs[h];
            float sm = 0.0f;
            for (int s = g; s < deg; s += 8) {
                float p = __expf(sc[s * HH + h] - mx);
                sc[s * HH + h] = p;
                sm += p;
            }
            red[g * HH + h] = sm;
        }
        __syncthreads();
        if (t < HH) {
            float sm = 0.0f;
            #pragma unroll
            for (int g = 0; g < 8; g++) sm += red[g * HH + t];
            invs[t] = 1.0f / sm;
        }
        __syncthreads();
        for (int i = t; i < deg * HH; i += 256)
            g_csr_attn[(size_t)beg * HH + i] = sc[i] * invs[i % HH];
    } else {
        // flush smem raw scores, then in-block global softmax (rare path)
        for (int i = t; i < DEGCAP * HH; i += 256)
            g_csr_attn[(size_t)beg * HH + i] = sc[i];
        __syncthreads();
        if (wid == 0 && lane < HH) {
            float mx = -3.0e38f;
            for (int s = 0; s < deg; s++)
                mx = fmaxf(mx, g_csr_attn[(size_t)(beg + s) * HH + lane]);
            float sm = 0.0f;
            for (int s = 0; s < deg; s++) {
                float p = __expf(g_csr_attn[(size_t)(beg + s) * HH + lane] - mx);
                g_csr_attn[(size_t)(beg + s) * HH + lane] = p;
                sm += p;
            }
            const float inv = 1.0f / sm;
            for (int s = 0; s < deg; s++)
                g_csr_attn[(size_t)(beg + s) * HH + lane] *= inv;
        }
    }

    if (t == 0) g_cnt[node] = 0;   // restore invariant for next call
}

// ---------------------------------------------------------------------------
// agg: hout[n] = 0.9 * sum attn*h[src] + 0.1 * v[n].
// 192 thr = 6 warps/node; warp owns 128 contiguous halves (2 heads).
// No __syncthreads, no smem: src/attn preloaded per 16-edge chunk into regs,
// broadcast via shfl. Last step (dst_split) writes bf16 split tiles.
// ---------------------------------------------------------------------------
__global__ __launch_bounds__(192) void agg_kernel(
    const __half* __restrict__ hin, __half* __restrict__ hout,
    __nv_bfloat16* __restrict__ dst_split)
{
    const int node = blockIdx.x;
    const int t    = threadIdx.x;
    const int w    = t >> 5, lane = t & 31;
    const int beg  = g_rowptr[node], end = g_rowptr[node + 1];
    const int col  = w * 128 + lane * 4;     // 4 contiguous halves, one head
    const int hsel = lane >> 4;              // 0 or 1 within warp's head pair

    float4 acc = {0.0f, 0.0f, 0.0f, 0.0f};

    for (int cs = beg; cs < end; cs += 16) {
        const int c = min(16, end - cs);
        int   src_r  = 0;
        float attn_r = 0.0f;
        if (lane < c) src_r = g_csr_src[cs + lane];
        {
            const int e = lane >> 1;
            if (e < c)
                attn_r = g_csr_attn[(size_t)(cs + e) * HH + (w * 2 + (lane & 1))];
        }
        #pragma unroll 4
        for (int j = 0; j < c; j++) {
            const int   srcj = __shfl_sync(0xFFFFFFFFu, src_r, j);
            const float wt   = __shfl_sync(0xFFFFFFFFu, attn_r, 2 * j + hsel);
            const uint2 pv = *reinterpret_cast<const uint2*>(
                hin + (size_t)srcj * DD + col);
            const float2 h0 = __half22float2(*reinterpret_cast<const __half2*>(&pv.x));
            const float2 h1 = __half22float2(*reinterpret_cast<const __half2*>(&pv.y));
            acc.x += wt * h0.x; acc.y += wt * h0.y;
            acc.z += wt * h1.x; acc.w += wt * h1.y;
        }
    }

    const uint2 vv = *reinterpret_cast<const uint2*>(
        g_vh + (size_t)node * DD + col);
    const float2 v0 = __half22float2(*reinterpret_cast<const __half2*>(&vv.x));
    const float2 v1 = __half22float2(*reinterpret_cast<const __half2*>(&vv.y));
    float4 o;
    o.x = 0.9f * acc.x + 0.1f * v0.x;
    o.y = 0.9f * acc.y + 0.1f * v0.y;
    o.z = 0.9f * acc.z + 0.1f * v1.x;
    o.w = 0.9f * acc.w + 0.1f * v1.y;

    if (dst_split) {
        float vals[4] = {o.x, o.y, o.z, o.w};
        __align__(8) __nv_bfloat16 hi[4], lo[4];
        #pragma unroll
        for (int j = 0; j < 4; j++) {
            hi[j] = __float2bfloat16(vals[j]);
            lo[j] = __float2bfloat16(vals[j] - __bfloat162float(hi[j]));
        }
        const int mtile = node >> 7, r = node & 127;
        #pragma unroll
        for (int seg = 0; seg < 3; seg++) {
            const int kp = col + seg * DD;
            const int kc = kp >> 6, cc = kp & 63;
            const size_t base = ((size_t)mtile * NCHUNK + kc) * (size_t)TILE_BYTES;
            uint32_t off = (uint32_t)(r * 128 + cc * 2);
            uint32_t sw  = off ^ ((off >> 3) & 0x70);
            *reinterpret_cast<uint2*>(reinterpret_cast<char*>(dst_split) + base + sw) =
                *reinterpret_cast<const uint2*>(seg == 2 ? lo : hi);
        }
    } else {
        __half2* op = reinterpret_cast<__half2*>(hout + (size_t)node * DD + col);
        op[0] = __floats2half2_rn(o.x, o.y);
        op[1] = __floats2half2_rn(o.z, o.w);
    }
}

// ---------------------------------------------------------------------------
// LayerNorm: block per row, 256 thr x 3 dims
// ---------------------------------------------------------------------------
__global__ __launch_bounds__(256) void ln_kernel(
    const float* __restrict__ y, const float* __restrict__ gamma,
    const float* __restrict__ beta, float* __restrict__ out)
{
    const int row = blockIdx.x;
    const int t   = threadIdx.x;
    const size_t base = (size_t)row * DD;

    const float x0 = y[base + t];
    const float x1 = y[base + t + 256];
    const float x2 = y[base + t + 512];

    __shared__ float sdata[256];
    sdata[t] = x0 + x1 + x2;
    __syncthreads();
    for (int off = 128; off > 0; off >>= 1) {
        if (t < off) sdata[t] += sdata[t + off];
        __syncthreads();
    }
    const float mu = sdata[0] * (1.0f / DD);
    __syncthreads();

    const float d0 = x0 - mu, d1 = x1 - mu, d2 = x2 - mu;
    sdata[t] = d0 * d0 + d1 * d1 + d2 * d2;
    __syncthreads();
    for (int off = 128; off > 0; off >>= 1) {
        if (t < off) sdata[t] += sdata[t + off];
        __syncthreads();
    }
    const float inv = rsqrtf(sdata[0] * (1.0f / DD) + 1e-12f);

    out[base + t]       = d0 * inv * gamma[t]       + beta[t];
    out[base + t + 256] = d1 * inv * gamma[t + 256] + beta[t + 256];
    out[base + t + 512] = d2 * inv * gamma[t + 512] + beta[t + 512];
}

// ---------------------------------------------------------------------------
// launch
// ---------------------------------------------------------------------------
static float* symF(const void* sym) {
    void* p = nullptr;
    cudaGetSymbolAddress(&p, sym);
    return (float*)p;
}
static __nv_bfloat16* symB(const void* sym) {
    void* p = nullptr;
    cudaGetSymbolAddress(&p, sym);
    return (__nv_bfloat16*)p;
}
static __half* symH(const void* sym) {
    void* p = nullptr;
    cudaGetSymbolAddress(&p, sym);
    return (__half*)p;
}

extern "C" void kernel_launch(void* const* d_in, const int* in_sizes, int n_in,
                              void* d_out, int out_size) {
    const float* x    = (const float*)d_in[0];
    const float* am   = (const float*)d_in[1];
    const int*   esrc = (const int*)d_in[2];
    const int*   edst = (const int*)d_in[3];
    const float* Wq   = (const float*)d_in[4];
    const float* bq   = (const float*)d_in[5];
    const float* Wk   = (const float*)d_in[6];
    const float* bk   = (const float*)d_in[7];
    const float* Wv   = (const float*)d_in[8];
    const float* bv   = (const float*)d_in[9];
    const float* Wo   = (const float*)d_in[10];
    const float* bo   = (const float*)d_in[11];
    const float* lng  = (const float*)d_in[12];
    const float* lnb  = (const float*)d_in[13];
    float* out = (float*)d_out;

    float* q  = symF(g_q);
    float* y  = symF(g_y);

    __half* kh  = symH(g_kh);
    __half* vh  = symH(g_vh);
    __half* hha = symH(g_hha);
    __half* hhb = symH(g_hhb);

    __nv_bfloat16* ax  = symB(g_ax);
    __nv_bfloat16* ah  = symB(g_ah);
    __nv_bfloat16* wqs = symB(g_wqs);
    __nv_bfloat16* wks = symB(g_wks);
    __nv_bfloat16* wvs = symB(g_wvs);
    __nv_bfloat16* wos = symB(g_wos);

    cudaFuncSetAttribute(gemm_qkv, cudaFuncAttributeMaxDynamicSharedMemorySize,
                         GEMM_SMEM);
    cudaFuncSetAttribute(gemm_one, cudaFuncAttributeMaxDynamicSharedMemorySize,
                         GEMM_SMEM);

    const int ACT_BLKS = (NN * GROUPS_PER_ROW) / 256;   // 9216
    const int W_BLKS   = (DD * GROUPS_PER_ROW) / 256;   // 864

    // CSR build first (no GEMM dependency; g_cnt==0 invariant at entry)
    count_kernel<<<(EE + 255) / 256, 256>>>(edst);
    scan_kernel<<<1, 1024>>>();
    scatter_kernel<<<(EE + 255) / 256, 256>>>(esrc, edst);

    // pack activations and all 4 weights into split-bf16 swizzled tile blocks
    split_pack_act<<<ACT_BLKS, 256>>>(x, ax);
    split_pack_w4<<<dim3(W_BLKS, 4), 256>>>(Wq, Wk, Wv, Wo,
                                            wqs, wks, wvs, wos);

    // fused q/k/v projections (q fp32; k,v fp16)
    gemm_qkv<<<dim3(18, 64), 256, GEMM_SMEM>>>(ax, wqs, wks, wvs,
                                               bq, bk, bv, q, kh, vh);

    // fused CSR-order scores + per-node softmax (+ g_cnt reset)
    score_softmax<<<NN, 256>>>(am);

    // 5 message-passing steps on fp16 h; last writes bf16 split tiles
    agg_kernel<<<NN, 192>>>(vh,  hha, nullptr);
    agg_kernel<<<NN, 192>>>(hha, hhb, nullptr);
    agg_kernel<<<NN, 192>>>(hhb, hha, nullptr);
    agg_kernel<<<NN, 192>>>(hha, hhb, nullptr);
    agg_kernel<<<NN, 192>>>(hhb, nullptr, ah);

    // output projection (+x residual), then LayerNorm
    gemm_one<<<dim3(6, 64), 256, GEMM_SMEM>>>(ah, wos, bo, x, y, 1.0f);
    ln_kernel<<<NN, 256>>>(y, lng, lnb, out);
}

// round 13
// speedup vs baseline: 2.6766x; 1.0244x over previous
#include <cuda_runtime.h>
#include <cuda_bf16.h>
#include <cuda_fp16.h>
#include <cstdint>

// ---------------------------------------------------------------------------
// Problem constants
// ---------------------------------------------------------------------------
#define NN    8192          // B*S nodes
#define DD    768           // hidden dim
#define HH    12            // heads
#define HDIM  64            // head dim
#define EE    131072        // edges
#define DEGCAP 128          // smem softmax capacity (max degree ~40 expected)

// split-bf16 GEMM constants
#define KSPLIT 2304         // 3*DD (hi|hi|lo vs hi|lo|hi)
#define NCHUNK 36           // KSPLIT/64
#define MT     128          // M tile
#define NT     128          // N tile
#define TILE_BYTES 16384    // 128 rows * 128 bytes
#define NSTAGE 4
#define GEMM_SMEM (NSTAGE * 2 * TILE_BYTES + 128)   // 128KB + pad

// ---------------------------------------------------------------------------
// Scratch (static device globals — no allocation allowed)
// ---------------------------------------------------------------------------
__device__ float g_q[NN * DD];
__device__ float g_y[NN * DD];

__device__ __half g_kh[NN * DD];         // k (fp16, score gather operand)
__device__ __half g_vh[NN * DD];         // v (fp16, gather + blend operand)
__device__ __half g_hha[NN * DD];        // intermediate h ping
__device__ __half g_hhb[NN * DD];        // intermediate h pong

__device__ int   g_cnt[NN];              // starts 0 (BSS); reset by score kernel
__device__ int   g_rowptr[NN + 1];
__device__ int   g_csr_src[EE];          // src node per CSR slot
__device__ float g_csr_attn[EE * HH];    // normalized attn (CSR order)

// split-bf16 operand storage (pre-swizzled 16KB tile blocks)
__device__ __align__(128) __nv_bfloat16 g_ax[(size_t)NN * KSPLIT];   // x  split
__device__ __align__(128) __nv_bfloat16 g_ah[(size_t)NN * KSPLIT];   // h  split
__device__ __align__(128) __nv_bfloat16 g_wqs[(size_t)DD * KSPLIT];
__device__ __align__(128) __nv_bfloat16 g_wks[(size_t)DD * KSPLIT];
__device__ __align__(128) __nv_bfloat16 g_wvs[(size_t)DD * KSPLIT];
__device__ __align__(128) __nv_bfloat16 g_wos[(size_t)DD * KSPLIT];

// ---------------------------------------------------------------------------
// helpers
// ---------------------------------------------------------------------------
__device__ __forceinline__ uint32_t smem_u32(const void* p) {
    uint32_t a;
    asm("{ .reg .u64 t; cvta.to.shared.u64 t, %1; cvt.u32.u64 %0, t; }"
        : "=r"(a) : "l"(p));
    return a;
}

__device__ __forceinline__ void ldmx4(uint32_t* r, uint32_t addr) {
    asm volatile("ldmatrix.sync.aligned.m8n8.x4.shared.b16 {%0,%1,%2,%3}, [%4];"
        : "=r"(r[0]), "=r"(r[1]), "=r"(r[2]), "=r"(r[3]) : "r"(addr));
}

__device__ __forceinline__ void mma_bf16(float* c, const uint32_t* a,
                                         uint32_t b0, uint32_t b1) {
    asm volatile(
        "mma.sync.aligned.m16n8k16.row.col.f32.bf16.bf16.f32 "
        "{%0,%1,%2,%3}, {%4,%5,%6,%7}, {%8,%9}, {%0,%1,%2,%3};"
        : "+f"(c[0]), "+f"(c[1]), "+f"(c[2]), "+f"(c[3])
        : "r"(a[0]), "r"(a[1]), "r"(a[2]), "r"(a[3]), "r"(b0), "r"(b1));
}

__device__ __forceinline__ void cp_chunk(uint32_t bufA, uint32_t bufW,
                                         const char* ga, const char* gw,
                                         int tid) {
    #pragma unroll
    for (int j = 0; j < 4; j++) {
        const uint32_t off = (uint32_t)(tid + j * 256) * 16;
        asm volatile("cp.async.cg.shared.global [%0], [%1], 16;"
            :: "r"(bufA + off), "l"(ga + off) : "memory");
        asm volatile("cp.async.cg.shared.global [%0], [%1], 16;"
            :: "r"(bufW + off), "l"(gw + off) : "memory");
    }
    asm volatile("cp.async.commit_group;" ::: "memory");
}

// ---------------------------------------------------------------------------
// split_pack (tile-block mapping): block = (kc, mtile[, wsel]).
// Writes one 16KB SW128 tile block; all indexing via shifts/masks.
// seg = kc/12 selects hi/hi/lo segment; lo_seg: 2=activation, 1=weight.
// ---------------------------------------------------------------------------
__device__ __forceinline__ void split_pack_tile_body(
    const float* __restrict__ src, __nv_bfloat16* __restrict__ dst,
    int lo_seg, int kc, int mtile)
{
    const int seg   = kc / 12;                 // 12 chunks of 64 per 768 seg
    const int kbase = kc * 64 - seg * DD;      // source col of chunk start
    const bool is_lo = (seg == lo_seg);
    char* out = reinterpret_cast<char*>(dst) +
                ((size_t)mtile * NCHUNK + kc) * (size_t)TILE_BYTES;
    const float* sbase = src + (size_t)mtile * 128 * DD + kbase;

    #pragma unroll
    for (int ii = 0; ii < 4; ii++) {
        const int i  = threadIdx.x + ii * 256;    // 0..1023
        const int r  = i >> 3;                    // row 0..127
        const int gg = i & 7;                     // 16B group in row
        const float* s = sbase + (size_t)r * DD + gg * 8;
        const float4 f0 = *reinterpret_cast<const float4*>(s);
        const float4 f1 = *reinterpret_cast<const float4*>(s + 4);
        float fv[8] = {f0.x, f0.y, f0.z, f0.w, f1.x, f1.y, f1.z, f1.w};

        __align__(16) __nv_bfloat16 vals[8];
        #pragma unroll
        for (int j = 0; j < 8; j++) {
            __nv_bfloat16 hi = __float2bfloat16(fv[j]);
            vals[j] = is_lo ? __float2bfloat16(fv[j] - __bfloat162float(hi))
                            : hi;
        }
        uint32_t off = (uint32_t)(r * 128 + gg * 16);
        uint32_t sw  = off ^ ((off >> 3) & 0x70);
        *reinterpret_cast<uint4*>(out + sw) =
            *reinterpret_cast<const uint4*>(vals);
    }
}

// activations: grid (NCHUNK, NN/128)
__global__ __launch_bounds__(256) void split_pack_act(
    const float* __restrict__ src, __nv_bfloat16* __restrict__ dst)
{
    split_pack_tile_body(src, dst, 2, blockIdx.x, blockIdx.y);
}

// all 4 weights: grid (NCHUNK, DD/128, 4)
__global__ __launch_bounds__(256) void split_pack_w4(
    const float* __restrict__ w0, const float* __restrict__ w1,
    const float* __restrict__ w2, const float* __restrict__ w3,
    __nv_bfloat16* __restrict__ d0, __nv_bfloat16* __restrict__ d1,
    __nv_bfloat16* __restrict__ d2, __nv_bfloat16* __restrict__ d3)
{
    const float* src; __nv_bfloat16* dst;
    switch (blockIdx.z) {
        case 0:  src = w0; dst = d0; break;
        case 1:  src = w1; dst = d1; break;
        case 2:  src = w2; dst = d2; break;
        default: src = w3; dst = d3; break;
    }
    split_pack_tile_body(src, dst, 1, blockIdx.x, blockIdx.y);
}

// ---------------------------------------------------------------------------
// GEMM core: CTA 128x128, 8 warps (4Mx2N), K'=2304 in 36 chunks of 64,
// 4-stage cp.async pipeline, ldmatrix + m16n8k16.
// Epilogue writes fp32 C (if non-null) and/or fp16 Ch (if non-null).
// ---------------------------------------------------------------------------
__device__ __forceinline__ void gemm_core(
    const char* Asrc, const char* Wsrc, const float* __restrict__ bias,
    const float* __restrict__ resid, float* __restrict__ C,
    __half* __restrict__ Ch, float scale, int mtile, int ncol, uint32_t sbase)
{
    const int tid  = threadIdx.x;
    const int wid  = tid >> 5, lane = tid & 31;
    const int wm   = wid & 3, wn = wid >> 2;

    float acc[2][8][4];
    #pragma unroll
    for (int mt = 0; mt < 2; mt++)
        #pragma unroll
        for (int nt = 0; nt < 8; nt++)
            #pragma unroll
            for (int j = 0; j < 4; j++) acc[mt][nt][j] = 0.0f;

    #pragma unroll
    for (int s = 0; s < NSTAGE - 1; s++) {
        const uint32_t bA = sbase + (uint32_t)s * (2 * TILE_BYTES);
        cp_chunk(bA, bA + TILE_BYTES,
                 Asrc + (size_t)s * TILE_BYTES, Wsrc + (size_t)s * TILE_BYTES,
                 tid);
    }

    for (int i = 0; i < NCHUNK; i++) {
        if (i <= NCHUNK - 3)
            asm volatile("cp.async.wait_group 2;" ::: "memory");
        else if (i == NCHUNK - 2)
            asm volatile("cp.async.wait_group 1;" ::: "memory");
        else
            asm volatile("cp.async.wait_group 0;" ::: "memory");
        __syncthreads();

        if (i + NSTAGE - 1 < NCHUNK) {
            const int s = (i + NSTAGE - 1) & (NSTAGE - 1);
            const uint32_t bA = sbase + (uint32_t)s * (2 * TILE_BYTES);
            cp_chunk(bA, bA + TILE_BYTES,
                     Asrc + (size_t)(i + NSTAGE - 1) * TILE_BYTES,
                     Wsrc + (size_t)(i + NSTAGE - 1) * TILE_BYTES, tid);
        }

        const uint32_t bufA = sbase + (uint32_t)(i & (NSTAGE - 1)) * (2 * TILE_BYTES);
        const uint32_t bufW = bufA + TILE_BYTES;

        #pragma unroll
        for (int ks = 0; ks < 4; ks++) {
            uint32_t a[2][4];
            #pragma unroll
            for (int mt = 0; mt < 2; mt++) {
                const int r = wm * 32 + mt * 16 + (lane & 15);
                const int gr = ks * 2 + (lane >> 4);
                ldmx4(a[mt], bufA + r * 128 + ((gr ^ (r & 7)) << 4));
            }
            uint32_t b[4][4];
            #pragma unroll
            for (int np = 0; np < 4; np++) {
                const int r = wn * 64 + np * 16 + (lane & 7) + ((lane >> 4) << 3);
                const int gr = ks * 2 + ((lane >> 3) & 1);
                ldmx4(b[np], bufW + r * 128 + ((gr ^ (r & 7)) << 4));
            }
            #pragma unroll
            for (int mt = 0; mt < 2; mt++)
                #pragma unroll
                for (int nt = 0; nt < 8; nt++)
                    mma_bf16(acc[mt][nt], a[mt],
                             b[nt >> 1][(nt & 1) * 2],
                             b[nt >> 1][(nt & 1) * 2 + 1]);
        }
    }

    const int row0 = mtile * MT + wm * 32;
    const int col0 = ncol * NT + wn * 64;
    #pragma unroll
    for (int mt = 0; mt < 2; mt++) {
        #pragma unroll
        for (int nt = 0; nt < 8; nt++) {
            const int r  = row0 + mt * 16 + (lane >> 2);
            const int cc = col0 + nt * 8 + (lane & 3) * 2;
            const float b0 = bias[cc], b1 = bias[cc + 1];
            float2 o0, o1;
            o0.x = (acc[mt][nt][0] + b0) * scale;
            o0.y = (acc[mt][nt][1] + b1) * scale;
            o1.x = (acc[mt][nt][2] + b0) * scale;
            o1.y = (acc[mt][nt][3] + b1) * scale;
            if (resid) {
                o0.x += resid[(size_t)r * DD + cc];
                o0.y += resid[(size_t)r * DD + cc + 1];
                o1.x += resid[(size_t)(r + 8) * DD + cc];
                o1.y += resid[(size_t)(r + 8) * DD + cc + 1];
            }
            if (C) {
                *reinterpret_cast<float2*>(C + (size_t)r * DD + cc)       = o0;
                *reinterpret_cast<float2*>(C + (size_t)(r + 8) * DD + cc) = o1;
            }
            if (Ch) {
                *reinterpret_cast<__half2*>(Ch + (size_t)r * DD + cc) =
                    __floats2half2_rn(o0.x, o0.y);
                *reinterpret_cast<__half2*>(Ch + (size_t)(r + 8) * DD + cc) =
                    __floats2half2_rn(o1.x, o1.y);
            }
        }
    }
}

// fused Q/K/V projection: grid (18, 64); blockIdx.x/6 selects the matrix
// q -> fp32 only; k -> fp16 only; v -> fp16 only
__global__ __launch_bounds__(256, 1)
void gemm_qkv(const __nv_bfloat16* __restrict__ Ab,
              const __nv_bfloat16* __restrict__ Wq,
              const __nv_bfloat16* __restrict__ Wk,
              const __nv_bfloat16* __restrict__ Wv,
              const float* __restrict__ bq, const float* __restrict__ bk,
              const float* __restrict__ bv,
              float* __restrict__ q, __half* __restrict__ kh,
              __half* __restrict__ vh)
{
    extern __shared__ char dyn_smem[];
    const uint32_t sbase = (smem_u32(dyn_smem) + 127u) & ~127u;
    const int sel  = blockIdx.x / 6;
    const int ncol = blockIdx.x % 6;
    const __nv_bfloat16* W = (sel == 0) ? Wq : (sel == 1) ? Wk : Wv;
    const float* bias      = (sel == 0) ? bq : (sel == 1) ? bk : bv;
    float*  C              = (sel == 0) ? q  : nullptr;
    __half* Ch             = (sel == 0) ? nullptr : (sel == 1) ? kh : vh;
    const float scale      = (sel == 0) ? 0.125f : 1.0f;

    gemm_core((const char*)Ab + (size_t)blockIdx.y * NCHUNK * TILE_BYTES,
              (const char*)W  + (size_t)ncol * NCHUNK * TILE_BYTES,
              bias, nullptr, C, Ch, scale, blockIdx.y, ncol, sbase);
}

// single GEMM (output projection): grid (6, 64)
__global__ __launch_bounds__(256, 1)
void gemm_one(const __nv_bfloat16* __restrict__ Ab,
              const __nv_bfloat16* __restrict__ Wb,
              const float* __restrict__ bias,
              const float* __restrict__ resid,
              float* __restrict__ C, float scale)
{
    extern __shared__ char dyn_smem[];
    const uint32_t sbase = (smem_u32(dyn_smem) + 127u) & ~127u;
    gemm_core((const char*)Ab + (size_t)blockIdx.y * NCHUNK * TILE_BYTES,
              (const char*)Wb + (size_t)blockIdx.x * NCHUNK * TILE_BYTES,
              bias, resid, C, nullptr, scale, blockIdx.y, blockIdx.x, sbase);
}

// ---------------------------------------------------------------------------
// CSR build (g_cnt == 0 at call entry; reset by score_softmax every call)
// ---------------------------------------------------------------------------
__global__ void count_kernel(const int* __restrict__ dst) {
    int e = blockIdx.x * blockDim.x + threadIdx.x;
    if (e < EE) atomicAdd(&g_cnt[dst[e]], 1);
}

__global__ __launch_bounds__(1024) void scan_kernel() {
    __shared__ int ssum[1024];
    const int t = threadIdx.x;
    const int base = t * 8;
    int local[8];
    int s = 0;
    #pragma unroll
    for (int i = 0; i < 8; i++) { local[i] = g_cnt[base + i]; s += local[i]; }
    ssum[t] = s;
    __syncthreads();
    for (int off = 1; off < 1024; off <<= 1) {
        int v = (t >= off) ? ssum[t - off] : 0;
        __syncthreads();
        ssum[t] += v;
        __syncthreads();
    }
    int pre = (t == 0) ? 0 : ssum[t - 1];
    #pragma unroll
    for (int i = 0; i < 8; i++) {
        g_rowptr[base + i] = pre;
        pre += local[i];
        g_cnt[base + i] = 0;               // reset for scatter pass
    }
    if (t == 1023) g_rowptr[NN] = pre;
}

__global__ void scatter_kernel(const int* __restrict__ src,
                               const int* __restrict__ dst) {
    int e = blockIdx.x * blockDim.x + threadIdx.x;
    if (e < EE) {
        int d = dst[e];
        int pos = g_rowptr[d] + atomicAdd(&g_cnt[d], 1);
        g_csr_src[pos] = src[e];
    }
}

// ---------------------------------------------------------------------------
// score_softmax: block per dst node. q (fp32) staged in smem; k gathered fp16;
// raw scores staged in smem; parallel per-head softmax; normalized attn
// written once to g_csr_attn. Global fallback for deg > DEGCAP.
// Also resets g_cnt[node] = 0 for the next call's count.
// ---------------------------------------------------------------------------
__global__ __launch_bounds__(256) void score_softmax(const float* __restrict__ am) {
    __shared__ float qs[DD];
    __shared__ float sc[DEGCAP * HH];
    __shared__ float red[8 * HH];
    __shared__ float mxs[HH], invs[HH];

    const int node = blockIdx.x;
    const int t    = threadIdx.x;
    const int wid  = t >> 5, lane = t & 31;

    qs[t]       = g_q[(size_t)node * DD + t];
    qs[t + 256] = g_q[(size_t)node * DD + t + 256];
    qs[t + 512] = g_q[(size_t)node * DD + t + 512];
    const bool m = (am[node] >= 0.0f);
    __syncthreads();

    const int beg = g_rowptr[node];
    const int deg = g_rowptr[node + 1] - beg;

    for (int s = wid; s < deg; s += 8) {
        const __half* kr = g_kh + (size_t)g_csr_src[beg + s] * DD;
        float myscore = 0.0f;
        #pragma unroll
        for (int h = 0; h < HH; h++) {
            const int i0 = h * HDIM + lane * 2;
            const float2 kf = __half22float2(
                *reinterpret_cast<const __half2*>(kr + i0));
            const float2 qf = *reinterpret_cast<const float2*>(qs + i0);
            float p = kf.x * qf.x + kf.y * qf.y;
            #pragma unroll
            for (int off = 16; off; off >>= 1)
                p += __shfl_xor_sync(0xFFFFFFFFu, p, off);
            if (lane == h) myscore = m ? p : -1.0e4f;
        }
        if (lane < HH) {
            if (s < DEGCAP) sc[s * HH + lane] = myscore;
            else g_csr_attn[(size_t)(beg + s) * HH + lane] = myscore;
        }
    }
    __syncthreads();

    if (deg <= DEGCAP) {
        if (t < 8 * HH) {
            const int h = t % HH, g = t / HH;
            float mx = -3.0e38f;
            for (int s = g; s < deg; s += 8) mx = fmaxf(mx, sc[s * HH + h]);
            red[g * HH + h] = mx;
        }
        __syncthreads();
        if (t < HH) {
            float mx = red[t];
            #pragma unroll
            for (int g = 1; g < 8; g++) mx = fmaxf(mx, red[g * HH + t]);
            mxs[t] = mx;
        }
        __syncthreads();
        if (t < 8 * HH) {
            const int h = t % HH, g = t / HH;
            const float mx = mxs[h];
            float sm = 0.0f;
            for (int s = g; s < deg; s += 8) {
                float p = __expf(sc[s * HH + h] - mx);
                sc[s * HH + h] = p;
                sm += p;
            }
            red[g * HH + h] = sm;
        }
        __syncthreads();
        if (t < HH) {
            float sm = 0.0f;
            #pragma unroll
            for (int g = 0; g < 8; g++) sm += red[g * HH + t];
            invs[t] = 1.0f / sm;
        }
        __syncthreads();
        for (int i = t; i < deg * HH; i += 256)
            g_csr_attn[(size_t)beg * HH + i] = sc[i] * invs[i % HH];
    } else {
        for (int i = t; i < DEGCAP * HH; i += 256)
            g_csr_attn[(size_t)beg * HH + i] = sc[i];
        __syncthreads();
        if (wid == 0 && lane < HH) {
            float mx = -3.0e38f;
            for (int s = 0; s < deg; s++)
                mx = fmaxf(mx, g_csr_attn[(size_t)(beg + s) * HH + lane]);
            float sm = 0.0f;
            for (int s = 0; s < deg; s++) {
                float p = __expf(g_csr_attn[(size_t)(beg + s) * HH + lane] - mx);
                g_csr_attn[(size_t)(beg + s) * HH + lane] = p;
                sm += p;
            }
            const float inv = 1.0f / sm;
            for (int s = 0; s < deg; s++)
                g_csr_attn[(size_t)(beg + s) * HH + lane] *= inv;
        }
    }

    if (t == 0) g_cnt[node] = 0;   // restore invariant for next call
}

// ---------------------------------------------------------------------------
// agg: hout[n] = 0.9 * sum attn*h[src] + 0.1 * v[n].
// 192 thr = 6 warps/node; warp owns 128 contiguous halves (2 heads).
// No __syncthreads, no smem: src/attn preloaded per 16-edge chunk into regs,
// broadcast via shfl. Last step (dst_split) writes bf16 split tiles.
// ---------------------------------------------------------------------------
__global__ __launch_bounds__(192) void agg_kernel(
    const __half* __restrict__ hin, __half* __restrict__ hout,
    __nv_bfloat16* __restrict__ dst_split)
{
    const int node = blockIdx.x;
    const int t    = threadIdx.x;
    const int w    = t >> 5, lane = t & 31;
    const int beg  = g_rowptr[node], end = g_rowptr[node + 1];
    const int col  = w * 128 + lane * 4;     // 4 contiguous halves, one head
    const int hsel = lane >> 4;              // 0 or 1 within warp's head pair

    float4 acc = {0.0f, 0.0f, 0.0f, 0.0f};

    for (int cs = beg; cs < end; cs += 16) {
        const int c = min(16, end - cs);
        int   src_r  = 0;
        float attn_r = 0.0f;
        if (lane < c) src_r = g_csr_src[cs + lane];
        {
            const int e = lane >> 1;
            if (e < c)
                attn_r = g_csr_attn[(size_t)(cs + e) * HH + (w * 2 + (lane & 1))];
        }
        #pragma unroll 4
        for (int j = 0; j < c; j++) {
            const int   srcj = __shfl_sync(0xFFFFFFFFu, src_r, j);
            const float wt   = __shfl_sync(0xFFFFFFFFu, attn_r, 2 * j + hsel);
            const uint2 pv = *reinterpret_cast<const uint2*>(
                hin + (size_t)srcj * DD + col);
            const float2 h0 = __half22float2(*reinterpret_cast<const __half2*>(&pv.x));
            const float2 h1 = __half22float2(*reinterpret_cast<const __half2*>(&pv.y));
            acc.x += wt * h0.x; acc.y += wt * h0.y;
            acc.z += wt * h1.x; acc.w += wt * h1.y;
        }
    }

    const uint2 vv = *reinterpret_cast<const uint2*>(
        g_vh + (size_t)node * DD + col);
    const float2 v0 = __half22float2(*reinterpret_cast<const __half2*>(&vv.x));
    const float2 v1 = __half22float2(*reinterpret_cast<const __half2*>(&vv.y));
    float4 o;
    o.x = 0.9f * acc.x + 0.1f * v0.x;
    o.y = 0.9f * acc.y + 0.1f * v0.y;
    o.z = 0.9f * acc.z + 0.1f * v1.x;
    o.w = 0.9f * acc.w + 0.1f * v1.y;

    if (dst_split) {
        float vals[4] = {o.x, o.y, o.z, o.w};
        __align__(8) __nv_bfloat16 hi[4], lo[4];
        #pragma unroll
        for (int j = 0; j < 4; j++) {
            hi[j] = __float2bfloat16(vals[j]);
            lo[j] = __float2bfloat16(vals[j] - __bfloat162float(hi[j]));
        }
        const int mtile = node >> 7, r = node & 127;
        #pragma unroll
        for (int seg = 0; seg < 3; seg++) {
            const int kp = col + seg * DD;
            const int kc = kp >> 6, cc = kp & 63;
            const size_t base = ((size_t)mtile * NCHUNK + kc) * (size_t)TILE_BYTES;
            uint32_t off = (uint32_t)(r * 128 + cc * 2);
            uint32_t sw  = off ^ ((off >> 3) & 0x70);
            *reinterpret_cast<uint2*>(reinterpret_cast<char*>(dst_split) + base + sw) =
                *reinterpret_cast<const uint2*>(seg == 2 ? lo : hi);
        }
    } else {
        __half2* op = reinterpret_cast<__half2*>(hout + (size_t)node * DD + col);
        op[0] = __floats2half2_rn(o.x, o.y);
        op[1] = __floats2half2_rn(o.z, o.w);
    }
}

// ---------------------------------------------------------------------------
// LayerNorm: block per row, 256 thr x 3 dims
// ---------------------------------------------------------------------------
__global__ __launch_bounds__(256) void ln_kernel(
    const float* __restrict__ y, const float* __restrict__ gamma,
    const float* __restrict__ beta, float* __restrict__ out)
{
    const int row = blockIdx.x;
    const int t   = threadIdx.x;
    const size_t base = (size_t)row * DD;

    const float x0 = y[base + t];
    const float x1 = y[base + t + 256];
    const float x2 = y[base + t + 512];

    __shared__ float sdata[256];
    sdata[t] = x0 + x1 + x2;
    __syncthreads();
    for (int off = 128; off > 0; off >>= 1) {
        if (t < off) sdata[t] += sdata[t + off];
        __syncthreads();
    }
    const float mu = sdata[0] * (1.0f / DD);
    __syncthreads();

    const float d0 = x0 - mu, d1 = x1 - mu, d2 = x2 - mu;
    sdata[t] = d0 * d0 + d1 * d1 + d2 * d2;
    __syncthreads();
    for (int off = 128; off > 0; off >>= 1) {
        if (t < off) sdata[t] += sdata[t + off];
        __syncthreads();
    }
    const float inv = rsqrtf(sdata[0] * (1.0f / DD) + 1e-12f);

    out[base + t]       = d0 * inv * gamma[t]       + beta[t];
    out[base + t + 256] = d1 * inv * gamma[t + 256] + beta[t + 256];
    out[base + t + 512] = d2 * inv * gamma[t + 512] + beta[t + 512];
}

// ---------------------------------------------------------------------------
// launch
// ---------------------------------------------------------------------------
static float* symF(const void* sym) {
    void* p = nullptr;
    cudaGetSymbolAddress(&p, sym);
    return (float*)p;
}
static __nv_bfloat16* symB(const void* sym) {
    void* p = nullptr;
    cudaGetSymbolAddress(&p, sym);
    return (__nv_bfloat16*)p;
}
static __half* symH(const void* sym) {
    void* p = nullptr;
    cudaGetSymbolAddress(&p, sym);
    return (__half*)p;
}

extern "C" void kernel_launch(void* const* d_in, const int* in_sizes, int n_in,
                              void* d_out, int out_size) {
    const float* x    = (const float*)d_in[0];
    const float* am   = (const float*)d_in[1];
    const int*   esrc = (const int*)d_in[2];
    const int*   edst = (const int*)d_in[3];
    const float* Wq   = (const float*)d_in[4];
    const float* bq   = (const float*)d_in[5];
    const float* Wk   = (const float*)d_in[6];
    const float* bk   = (const float*)d_in[7];
    const float* Wv   = (const float*)d_in[8];
    const float* bv   = (const float*)d_in[9];
    const float* Wo   = (const float*)d_in[10];
    const float* bo   = (const float*)d_in[11];
    const float* lng  = (const float*)d_in[12];
    const float* lnb  = (const float*)d_in[13];
    float* out = (float*)d_out;

    float* q  = symF(g_q);
    float* y  = symF(g_y);

    __half* kh  = symH(g_kh);
    __half* vh  = symH(g_vh);
    __half* hha = symH(g_hha);
    __half* hhb = symH(g_hhb);

    __nv_bfloat16* ax  = symB(g_ax);
    __nv_bfloat16* ah  = symB(g_ah);
    __nv_bfloat16* wqs = symB(g_wqs);
    __nv_bfloat16* wks = symB(g_wks);
    __nv_bfloat16* wvs = symB(g_wvs);
    __nv_bfloat16* wos = symB(g_wos);

    cudaFuncSetAttribute(gemm_qkv, cudaFuncAttributeMaxDynamicSharedMemorySize,
                         GEMM_SMEM);
    cudaFuncSetAttribute(gemm_one, cudaFuncAttributeMaxDynamicSharedMemorySize,
                         GEMM_SMEM);

    // launch order chosen so the 4th launch (ncu capture slot) is gemm_qkv
    // 1) activation pack   2) weight packs   3) edge count   4) QKV GEMM
    split_pack_act<<<dim3(NCHUNK, NN / 128), 256>>>(x, ax);
    split_pack_w4<<<dim3(NCHUNK, DD / 128, 4), 256>>>(Wq, Wk, Wv, Wo,
                                                      wqs, wks, wvs, wos);
    count_kernel<<<(EE + 255) / 256, 256>>>(edst);
    gemm_qkv<<<dim3(18, 64), 256, GEMM_SMEM>>>(ax, wqs, wks, wvs,
                                               bq, bk, bv, q, kh, vh);

    // finish CSR build
    scan_kernel<<<1, 1024>>>();
    scatter_kernel<<<(EE + 255) / 256, 256>>>(esrc, edst);

    // fused CSR-order scores + per-node softmax (+ g_cnt reset)
    score_softmax<<<NN, 256>>>(am);

    // 5 message-passing steps on fp16 h; last writes bf16 split tiles
    agg_kernel<<<NN, 192>>>(vh,  hha, nullptr);
    agg_kernel<<<NN, 192>>>(hha, hhb, nullptr);
    agg_kernel<<<NN, 192>>>(hhb, hha, nullptr);
    agg_kernel<<<NN, 192>>>(hha, hhb, nullptr);
    agg_kernel<<<NN, 192>>>(hhb, nullptr, ah);

    // output projection (+x residual), then LayerNorm
    gemm_one<<<dim3(6, 64), 256, GEMM_SMEM>>>(ah, wos, bo, x, y, 1.0f);
    ln_kernel<<<NN, 256>>>(y, lng, lnb, out);
}